// round 13
// baseline (speedup 1.0000x reference)
#include <cuda_runtime.h>
#include <cuda_bf16.h>
#include <math.h>

#define T_DIM 128
#define B_DIM 64
#define C_DIM 768
#define M_DIM (T_DIM * B_DIM)   // 8192
#define K_DW  31
#define EPSF  1e-5f
#define NMW   24                 // mask words per row (768/32)

typedef unsigned long long ull;
typedef unsigned int uint32;
typedef unsigned short ushort;

// ---------------- scratch ----------------
__device__ float g_Y1 [M_DIM * C_DIM];
__device__ float g_Y2 [M_DIM * 2 * C_DIM];
__device__ float g_Y3 [M_DIM * C_DIM];
__device__ uint32 g_S2m[M_DIM * NMW];            // spike masks after dw path
__device__ uint32 g_Sgm[M_DIM * NMW];            // gate spike masks
__device__ float g_W2t[C_DIM * 2 * C_DIM];       // pw2_w transposed [k][n]
__device__ float g_Wgt[C_DIM * C_DIM];           // gsu_w transposed [k][n]
__device__ __nv_bfloat16 g_Hh[M_DIM * C_DIM];
__device__ __nv_bfloat16 g_Hm[M_DIM * C_DIM];
__device__ __nv_bfloat16 g_Hl[M_DIM * C_DIM];
__device__ __nv_bfloat16 g_W1hi[C_DIM * C_DIM];
__device__ __nv_bfloat16 g_W1mi[C_DIM * C_DIM];
__device__ __nv_bfloat16 g_W1lo[C_DIM * C_DIM];

// ---------------- helpers ----------------
__device__ __forceinline__ void mma_bf16(float* c, const uint32* a, uint32 b0, uint32 b1) {
    asm volatile(
        "mma.sync.aligned.m16n8k16.row.col.f32.bf16.bf16.f32 "
        "{%0,%1,%2,%3}, {%4,%5,%6,%7}, {%8,%9}, {%0,%1,%2,%3};"
        : "+f"(c[0]), "+f"(c[1]), "+f"(c[2]), "+f"(c[3])
        : "r"(a[0]), "r"(a[1]), "r"(a[2]), "r"(a[3]), "r"(b0), "r"(b1));
}
__device__ __forceinline__ void ldsm4(uint32* r, uint32 saddr) {
    asm volatile("ldmatrix.sync.aligned.m8n8.x4.shared.b16 {%0,%1,%2,%3}, [%4];"
        : "=r"(r[0]), "=r"(r[1]), "=r"(r[2]), "=r"(r[3]) : "r"(saddr));
}
__device__ __forceinline__ ull add2(ull a, ull b) {
    ull r; asm("add.rn.f32x2 %0, %1, %2;" : "=l"(r) : "l"(a), "l"(b)); return r;
}
__device__ __forceinline__ float2 unpack2(ull v) {
    float2 r; asm("mov.b64 {%0, %1}, %2;" : "=f"(r.x), "=f"(r.y) : "l"(v)); return r;
}
#define CP16(dst, src) \
    asm volatile("cp.async.cg.shared.global [%0], [%1], 16;" :: "r"(dst), "l"(src))
#define CP_COMMIT() asm volatile("cp.async.commit_group;" ::: "memory")
#define CP_WAIT1()  asm volatile("cp.async.wait_group 1;" ::: "memory")
#define CP_WAIT0()  asm volatile("cp.async.wait_group 0;" ::: "memory")

// ---------------- weight split (W1 only) ----------------
__global__ void __launch_bounds__(256) split_w_kernel(
    const float* __restrict__ W,
    __nv_bfloat16* __restrict__ hi, __nv_bfloat16* __restrict__ mi,
    __nv_bfloat16* __restrict__ lo, int n)
{
    int i = blockIdx.x * blockDim.x + threadIdx.x;
    if (i >= n) return;
    float w = W[i];
    __nv_bfloat16 h = __float2bfloat16(w);
    float r1 = w - __bfloat162float(h);
    __nv_bfloat16 m = __float2bfloat16(r1);
    float r2 = r1 - __bfloat162float(m);
    hi[i] = h; mi[i] = m; lo[i] = __float2bfloat16(r2);
}

// ---------------- transpose: in[R][C] -> out[C][R] ----------------
__global__ void __launch_bounds__(256) transpose_kernel(
    const float* __restrict__ in, float* __restrict__ out, int R, int C)
{
    __shared__ float t[32][33];
    int r0 = blockIdx.y * 32, c0 = blockIdx.x * 32;
    int x = threadIdx.x, y0 = threadIdx.y;     // block (32, 8)
    #pragma unroll
    for (int dy = 0; dy < 32; dy += 8)
        t[y0 + dy][x] = in[(size_t)(r0 + y0 + dy) * C + c0 + x];
    __syncthreads();
    #pragma unroll
    for (int dy = 0; dy < 32; dy += 8)
        out[(size_t)(c0 + y0 + dy) * R + r0 + x] = t[x][y0 + dy];
}

// ---------------- block reduction helper ----------------
__inline__ __device__ float block_reduce_sum(float val, float* shmem) {
    int tid = threadIdx.x;
    #pragma unroll
    for (int o = 16; o > 0; o >>= 1) val += __shfl_xor_sync(0xffffffffu, val, o);
    if ((tid & 31) == 0) shmem[tid >> 5] = val;
    __syncthreads();
    float r = 0.0f;
    if (tid < 8) r = shmem[tid];
    if (tid < 32) {
        #pragma unroll
        for (int o = 4; o > 0; o >>= 1) r += __shfl_xor_sync(0xffffffffu, r, o);
    }
    if (tid == 0) shmem[0] = r;
    __syncthreads();
    r = shmem[0];
    __syncthreads();
    return r;
}

// ---------------- layernorm -> 3-way bf16 split output ----------------
__global__ void __launch_bounds__(256) ln_kernel(
    const float* __restrict__ x, const float* __restrict__ gam,
    const float* __restrict__ bet,
    __nv_bfloat16* __restrict__ Hh, __nv_bfloat16* __restrict__ Hm,
    __nv_bfloat16* __restrict__ Hl)
{
    __shared__ float red[32];
    int row = blockIdx.x;
    const float* xr = x + (size_t)row * C_DIM;
    int tid = threadIdx.x;

    float lx[3];
    float s = 0.0f;
    #pragma unroll
    for (int i = 0; i < 3; i++) { lx[i] = xr[tid + i * 256]; s += lx[i]; }
    float mean = block_reduce_sum(s, red) * (1.0f / C_DIM);

    float s2 = 0.0f;
    #pragma unroll
    for (int i = 0; i < 3; i++) { float d = lx[i] - mean; s2 += d * d; }
    float var = block_reduce_sum(s2, red) * (1.0f / C_DIM);
    float rstd = 1.0f / sqrtf(var + EPSF);

    #pragma unroll
    for (int i = 0; i < 3; i++) {
        int c = tid + i * 256;
        float y = (lx[i] - mean) * rstd * gam[c] + bet[c];
        __nv_bfloat16 h = __float2bfloat16(y);
        float r1 = y - __bfloat162float(h);
        __nv_bfloat16 m = __float2bfloat16(r1);
        float r2 = r1 - __bfloat162float(m);
        size_t idx = (size_t)row * C_DIM + c;
        Hh[idx] = h; Hm[idx] = m; Hl[idx] = __float2bfloat16(r2);
    }
}

// ================= dense GEMM1 (6-term bf16 split, mma) =================
#define GBM 128
#define GBN 64
#define GBK 32
#define ASTR 40

#define S6_AH (GBM * ASTR)
#define S6_BH (GBN * ASTR)
#define S6_STG (3 * S6_AH + 3 * S6_BH)
#define S6_SMEM (2 * S6_STG * 2)

__global__ void __launch_bounds__(256) gemm_split6_bf16(
    const __nv_bfloat16* __restrict__ Ah, const __nv_bfloat16* __restrict__ Am,
    const __nv_bfloat16* __restrict__ Al,
    const __nv_bfloat16* __restrict__ Wh, const __nv_bfloat16* __restrict__ Wm,
    const __nv_bfloat16* __restrict__ Wl,
    const float* __restrict__ bias, const float* __restrict__ bnp,
    float* __restrict__ Out, int M, int N, int K)
{
    extern __shared__ __align__(16) unsigned short sm[];
    uint32 smb = (uint32)__cvta_generic_to_shared(sm);

    int tid = threadIdx.x;
    int wid = tid >> 5, lane = tid & 31;
    int wm = wid & 3, wn = wid >> 2;
    int bn0 = blockIdx.x * GBN, bm0 = blockIdx.y * GBM;

    int ldrow = tid >> 2;
    int ldcol = (tid & 3) * 8;

    const __nv_bfloat16* Asel[3] = {Ah, Am, Al};
    const __nv_bfloat16* Wsel[3] = {Wh, Wm, Wl};

    float acc[2][4][4];
    #pragma unroll
    for (int mt = 0; mt < 2; mt++)
        #pragma unroll
        for (int nt = 0; nt < 4; nt++)
            #pragma unroll
            for (int q = 0; q < 4; q++) acc[mt][nt][q] = 0.0f;

    int a_row = (lane & 7) + ((lane >> 3) & 1) * 8;
    int a_ko  = ((lane >> 4) & 1) * 8;
    int b_row = (lane & 7) + ((lane >> 4) & 1) * 8;
    int b_ko  = ((lane >> 3) & 1) * 8;

    auto issue = [&](int st, int k0) {
        #pragma unroll
        for (int s = 0; s < 3; s++) {
            #pragma unroll
            for (int j = 0; j < 2; j++) {
                int row = ldrow + j * 64;
                uint32 dst = smb + (uint32)(st * S6_STG + s * S6_AH + row * ASTR + ldcol) * 2;
                CP16(dst, Asel[s] + (size_t)(bm0 + row) * K + k0 + ldcol);
            }
            uint32 dst = smb + (uint32)(st * S6_STG + 3 * S6_AH + s * S6_BH + ldrow * ASTR + ldcol) * 2;
            CP16(dst, Wsel[s] + (size_t)(bn0 + ldrow) * K + k0 + ldcol);
        }
    };

    int NCH = K / GBK;
    issue(0, 0);
    CP_COMMIT();

    for (int ch = 0; ch < NCH; ch++) {
        if (ch + 1 < NCH) issue((ch + 1) & 1, (ch + 1) * GBK);
        CP_COMMIT();
        CP_WAIT1();
        __syncthreads();

        int st = ch & 1;
        uint32 abase = smb + (uint32)(st * S6_STG) * 2;
        uint32 bbase = smb + (uint32)(st * S6_STG + 3 * S6_AH) * 2;

        #pragma unroll
        for (int ks = 0; ks < 2; ks++) {
            int kc = ks * 16;
            uint32 af[3][2][4];
            #pragma unroll
            for (int s = 0; s < 3; s++)
                #pragma unroll
                for (int mt = 0; mt < 2; mt++)
                    ldsm4(af[s][mt], abase + (uint32)(s * S6_AH + (wm * 32 + mt * 16 + a_row) * ASTR + kc + a_ko) * 2);
            #pragma unroll
            for (int t = 0; t < 3; t++) {
                #pragma unroll
                for (int g = 0; g < 2; g++) {
                    uint32 bf[4];
                    ldsm4(bf, bbase + (uint32)(t * S6_BH + (wn * 32 + g * 16 + b_row) * ASTR + kc + b_ko) * 2);
                    #pragma unroll
                    for (int s = 0; s < 3; s++) {
                        if (s + t <= 2) {
                            mma_bf16(acc[0][2 * g],     af[s][0], bf[0], bf[1]);
                            mma_bf16(acc[1][2 * g],     af[s][1], bf[0], bf[1]);
                            mma_bf16(acc[0][2 * g + 1], af[s][0], bf[2], bf[3]);
                            mma_bf16(acc[1][2 * g + 1], af[s][1], bf[2], bf[3]);
                        }
                    }
                }
            }
        }
        __syncthreads();
    }

    int r4 = lane >> 2, c2 = (lane & 3) * 2;
    #pragma unroll
    for (int nt = 0; nt < 4; nt++) {
        int n0 = bn0 + wn * 32 + nt * 8 + c2;
        float g0 = bnp[n0],     be0 = bnp[N + n0],     mm0 = bnp[2*N + n0],     vv0 = bnp[3*N + n0];
        float g1 = bnp[n0 + 1], be1 = bnp[N + n0 + 1], mm1 = bnp[2*N + n0 + 1], vv1 = bnp[3*N + n0 + 1];
        float sc0 = g0 / sqrtf(vv0 + EPSF), sh0 = be0 - mm0 * sc0;
        float sc1 = g1 / sqrtf(vv1 + EPSF), sh1 = be1 - mm1 * sc1;
        float bs0 = bias[n0], bs1 = bias[n0 + 1];
        #pragma unroll
        for (int mt = 0; mt < 2; mt++) {
            int m0 = bm0 + wm * 32 + mt * 16 + r4;
            float2 o0, o1;
            o0.x = (acc[mt][nt][0] + bs0) * sc0 + sh0;
            o0.y = (acc[mt][nt][1] + bs1) * sc1 + sh1;
            o1.x = (acc[mt][nt][2] + bs0) * sc0 + sh0;
            o1.y = (acc[mt][nt][3] + bs1) * sc1 + sh1;
            *(float2*)&Out[(size_t)m0 * N + n0] = o0;
            *(float2*)&Out[(size_t)(m0 + 8) * N + n0] = o1;
        }
    }
}

// ================= sparse spike GEMM =================
// Out[m,n] = ((sum_{k in mask(m)} Wt[k][n]) + bias[n]) * bn_sc + bn_sh
// W slab [768][64] resident in smem; masks decoded warp-uniform (ascending k).
#define SP_SMEM (C_DIM * 64 * 4)     // 196608

__global__ void __launch_bounds__(256) gemm_sparse(
    const uint32* __restrict__ mask,   // [M][NMW]
    const float* __restrict__ Wt,      // [768][N]
    const float* __restrict__ bias, const float* __restrict__ bnp,
    float* __restrict__ Out, int N, int mPerCTA)
{
    extern __shared__ __align__(16) float Ws[];   // [768][64]
    int tid = threadIdx.x, wid = tid >> 5, lane = tid & 31;
    int n0 = blockIdx.x * 64;
    int mbase = blockIdx.y * mPerCTA;

    // load W slab (768 x 64 floats)
    #pragma unroll 4
    for (int i = 0; i < 48; i++) {
        int e = tid + i * 256;
        int row = e >> 4, cg = e & 15;
        uint32 dst = (uint32)__cvta_generic_to_shared(Ws + row * 64 + cg * 4);
        CP16(dst, Wt + (size_t)row * N + n0 + cg * 4);
    }
    CP_COMMIT(); CP_WAIT0(); __syncthreads();

    int n = n0 + lane * 2;
    float bs0 = bias[n], bs1 = bias[n + 1];
    float g0 = bnp[n],     be0 = bnp[N + n],     mm0 = bnp[2*N + n],     vv0 = bnp[3*N + n];
    float g1 = bnp[n + 1], be1 = bnp[N + n + 1], mm1 = bnp[2*N + n + 1], vv1 = bnp[3*N + n + 1];
    float sc0 = g0 / sqrtf(vv0 + EPSF), sh0 = be0 - mm0 * sc0;
    float sc1 = g1 / sqrtf(vv1 + EPSF), sh1 = be1 - mm1 * sc1;

    int mw = mPerCTA >> 3;               // rows per warp
    const ull* Ws2 = (const ull*)Ws;
    for (int i = 0; i < mw; i++) {
        int m = mbase + wid * mw + i;
        ull acc = 0ull;
        const uint32* mp = mask + (size_t)m * NMW;
        #pragma unroll 4
        for (int j = 0; j < NMW; j++) {
            uint32 bm = __ldg(mp + j);
            int kb = j * 32;
            while (bm) {
                int kk = __ffs(bm) - 1;
                bm &= bm - 1;
                acc = add2(acc, Ws2[(kb + kk) * 32 + lane]);
            }
        }
        float2 v = unpack2(acc);
        float2 o;
        o.x = (v.x + bs0) * sc0 + sh0;
        o.y = (v.y + bs1) * sc1 + sh1;
        *(float2*)&Out[(size_t)m * N + n] = o;
    }
}

// ---------------- fused lif1 -> depthwise -> bn2+lif2 -> spike MASKS ---------
#define DW_PAD 15
#define LD_SXP_ROWS (T_DIM + 2 * DW_PAD)
#define LIFDW_SMEM (LD_SXP_ROWS * 64 * 4 + T_DIM * 64 * 4)

__global__ void __launch_bounds__(256) lifdw_kernel(
    const float* __restrict__ Y1, const float* __restrict__ w,
    const float* __restrict__ bvec, const float* __restrict__ bn2p,
    uint32* __restrict__ S2m)
{
    extern __shared__ __align__(16) char smraw[];
    float (*sxp)[64] = (float(*)[64])smraw;
    float (*sd)[64]  = (float(*)[64])(smraw + LD_SXP_ROWS * 64 * 4);

    int b  = blockIdx.x;
    int c0 = blockIdx.y * 64;
    int tid = threadIdx.x;

    for (int i = tid; i < 2 * DW_PAD * 64; i += 256) {
        int r = i >> 6, ci = i & 63;
        if (r < DW_PAD) sxp[r][ci] = 0.0f;
        else            sxp[T_DIM + DW_PAD + (r - DW_PAD)][ci] = 0.0f;
    }
    for (int i = tid; i < T_DIM * 64; i += 256) {
        int t = i >> 6, ci = i & 63;
        sxp[t + DW_PAD][ci] = Y1[((size_t)t * B_DIM + b) * C_DIM + c0 + ci];
    }
    __syncthreads();

    // lif1 scan in place
    if (tid < 64) {
        float v = 0.0f;
        #pragma unroll 4
        for (int t = 0; t < T_DIM; t++) {
            v = v * 0.5f + sxp[t + DW_PAD][tid];
            float s = (v >= 1.0f) ? 1.0f : 0.0f;
            v = (s > 0.0f) ? 0.0f : v;
            sxp[t + DW_PAD][tid] = s;
        }
    }
    __syncthreads();

    // depthwise conv
    {
        int ci = tid & 63;
        int tg = tid >> 6;
        int c  = c0 + ci;
        int t0 = tg * 32;

        float wr[K_DW];
        #pragma unroll
        for (int k = 0; k < K_DW; k++) wr[k] = w[c * K_DW + k];
        float bb = bvec[c];

        float acc[32];
        #pragma unroll
        for (int i = 0; i < 32; i++) acc[i] = bb;

        #pragma unroll
        for (int dt = -DW_PAD; dt <= 31 + DW_PAD; dt++) {
            float sv = sxp[t0 + dt + DW_PAD][ci];
            #pragma unroll
            for (int i = 0; i < 32; i++) {
                int k = dt - i + DW_PAD;
                if (k >= 0 && k < K_DW) acc[i] += sv * wr[k];
            }
        }
        __syncthreads();
        #pragma unroll
        for (int i = 0; i < 32; i++) sd[t0 + i][ci] = acc[i];
    }
    __syncthreads();

    // bn2 + lif2 scan -> ballot -> mask words (word j = c0/32 + warp)
    if (tid < 64) {
        int c = c0 + tid;
        int jw = (c0 >> 5) + (tid >> 5);        // this warp's mask word index
        float g = bn2p[c], be = bn2p[C_DIM + c], mm = bn2p[2 * C_DIM + c], vv = bn2p[3 * C_DIM + c];
        float sc = g / sqrtf(vv + EPSF);
        float sh = be - mm * sc;
        float v = 0.0f;
        for (int t = 0; t < T_DIM; t++) {
            float xv = sd[t][tid] * sc + sh;
            v = v * 0.5f + xv;
            float s = (v >= 1.0f) ? 1.0f : 0.0f;
            v = (s > 0.0f) ? 0.0f : v;
            uint32 bal = __ballot_sync(0xffffffffu, s > 0.0f);
            if ((tid & 31) == 0)
                S2m[((size_t)t * B_DIM + b) * NMW + jw] = bal;
        }
    }
}

// ---------------- gate LIF -> spike masks ----------------
// grid (B_DIM, 2); 384 threads cover half the channels each.
__global__ void __launch_bounds__(384) gate_mask_kernel(
    const float* __restrict__ Y2, uint32* __restrict__ Sgm)
{
    int b = blockIdx.x;
    int c = blockIdx.y * 384 + threadIdx.x;
    int jw = c >> 5;
    const float* xp = Y2 + (size_t)b * 2 * C_DIM + C_DIM + c;
    size_t stx = (size_t)B_DIM * 2 * C_DIM;

    float v = 0.0f;
    for (int t = 0; t < T_DIM; t++) {
        float xv = xp[(size_t)t * stx];
        v = v * 0.5f + xv;
        float s = (v >= 1.0f) ? 1.0f : 0.0f;
        v = (s > 0.0f) ? 0.0f : v;
        uint32 bal = __ballot_sync(0xffffffffu, s > 0.0f);
        if ((threadIdx.x & 31) == 0)
            Sgm[((size_t)t * B_DIM + b) * NMW + jw] = bal;
    }
}

// ---------------- fused final double-LIF ----------------
__global__ void __launch_bounds__(256) lif_final_kernel(
    const float* __restrict__ Y3, const float* __restrict__ Y2out,
    float* __restrict__ Out)
{
    int j = blockIdx.x * blockDim.x + threadIdx.x;
    if (j >= B_DIM * C_DIM) return;
    int b = j / C_DIM, c = j % C_DIM;
    const float* yp = Y3 + (size_t)b * C_DIM + c;
    const float* op = Y2out + (size_t)b * 2 * C_DIM + c;
    float* sp = Out + (size_t)j;
    size_t st3 = (size_t)B_DIM * C_DIM;
    size_t st2 = (size_t)B_DIM * 2 * C_DIM;

    float v9 = 0.0f, v10 = 0.0f;
    #pragma unroll 4
    for (int t = 0; t < T_DIM; t++) {
        float g = yp[(size_t)t * st3];
        v9 = v9 * 0.5f + g;
        float s9 = (v9 >= 1.0f) ? 1.0f : 0.0f;
        v9 = (s9 > 0.0f) ? 0.0f : v9;
        float x = op[(size_t)t * st2] * s9;
        v10 = v10 * 0.5f + x;
        float s10 = (v10 >= 1.0f) ? 1.0f : 0.0f;
        v10 = (s10 > 0.0f) ? 0.0f : v10;
        sp[(size_t)t * st3] = s10;
    }
}

// ---------------- launch ----------------
extern "C" void kernel_launch(void* const* d_in, const int* in_sizes, int n_in,
                              void* d_out, int out_size)
{
    const float* x        = (const float*)d_in[0];
    const float* ln_g     = (const float*)d_in[1];
    const float* ln_b     = (const float*)d_in[2];
    const float* pw1_w    = (const float*)d_in[3];
    const float* pw1_b    = (const float*)d_in[4];
    const float* bn1_p    = (const float*)d_in[5];
    const float* dw_w     = (const float*)d_in[6];
    const float* dw_b     = (const float*)d_in[7];
    const float* bn2_p    = (const float*)d_in[8];
    const float* pw2_w    = (const float*)d_in[9];
    const float* pw2_b    = (const float*)d_in[10];
    const float* bn3_p    = (const float*)d_in[11];
    const float* gsu_w    = (const float*)d_in[12];
    const float* gsu_b    = (const float*)d_in[13];
    const float* gsu_bn_p = (const float*)d_in[14];

    float *Y1, *Y2, *Y3, *W2t, *Wgt;
    uint32 *S2m, *Sgm;
    __nv_bfloat16 *Hh, *Hm, *Hl, *W1hi, *W1mi, *W1lo;
    cudaGetSymbolAddress((void**)&Y1,   g_Y1);
    cudaGetSymbolAddress((void**)&Y2,   g_Y2);
    cudaGetSymbolAddress((void**)&Y3,   g_Y3);
    cudaGetSymbolAddress((void**)&S2m,  g_S2m);
    cudaGetSymbolAddress((void**)&Sgm,  g_Sgm);
    cudaGetSymbolAddress((void**)&W2t,  g_W2t);
    cudaGetSymbolAddress((void**)&Wgt,  g_Wgt);
    cudaGetSymbolAddress((void**)&Hh,   g_Hh);
    cudaGetSymbolAddress((void**)&Hm,   g_Hm);
    cudaGetSymbolAddress((void**)&Hl,   g_Hl);
    cudaGetSymbolAddress((void**)&W1hi, g_W1hi);
    cudaGetSymbolAddress((void**)&W1mi, g_W1mi);
    cudaGetSymbolAddress((void**)&W1lo, g_W1lo);

    // idempotent, every invocation
    cudaFuncSetAttribute(gemm_split6_bf16,
        cudaFuncAttributeMaxDynamicSharedMemorySize, S6_SMEM);
    cudaFuncSetAttribute(gemm_sparse,
        cudaFuncAttributeMaxDynamicSharedMemorySize, SP_SMEM);
    cudaFuncSetAttribute(lifdw_kernel,
        cudaFuncAttributeMaxDynamicSharedMemorySize, LIFDW_SMEM);

    const int lif_blocks = (B_DIM * C_DIM + 255) / 256;   // 192

    // 0) W1 split + W2/Wg transposes
    split_w_kernel<<<(C_DIM * C_DIM + 255) / 256, 256>>>(pw1_w, W1hi, W1mi, W1lo, C_DIM * C_DIM);
    transpose_kernel<<<dim3(C_DIM / 32, 2 * C_DIM / 32), dim3(32, 8)>>>(pw2_w, W2t, 2 * C_DIM, C_DIM);
    transpose_kernel<<<dim3(C_DIM / 32, C_DIM / 32), dim3(32, 8)>>>(gsu_w, Wgt, C_DIM, C_DIM);

    // 1) LayerNorm -> H splits
    ln_kernel<<<M_DIM, 256>>>(x, ln_g, ln_b, Hh, Hm, Hl);

    // 2) pw1 + bias + bn1 (dense mma, 6-term split)
    gemm_split6_bf16<<<dim3(C_DIM / GBN, M_DIM / GBM), 256, S6_SMEM>>>(
        Hh, Hm, Hl, W1hi, W1mi, W1lo, pw1_b, bn1_p, Y1, M_DIM, C_DIM, C_DIM);

    // 3-5) fused: lif1 -> depthwise -> bn2+lif2 -> spike MASKS
    lifdw_kernel<<<dim3(B_DIM, C_DIM / 64), 256, LIFDW_SMEM>>>(
        Y1, dw_w, dw_b, bn2_p, S2m);

    // 6) pw2 + bias + bn3 (SPARSE: masked column-sums of fp32 weights)
    gemm_sparse<<<dim3(2 * C_DIM / 64, 16), 256, SP_SMEM>>>(
        S2m, W2t, pw2_b, bn3_p, Y2, 2 * C_DIM, M_DIM / 16);

    // 7) gate LIF -> masks
    gate_mask_kernel<<<dim3(B_DIM, 2), 384>>>(Y2, Sgm);

    // 8) gsu GEMM (SPARSE)
    gemm_sparse<<<dim3(C_DIM / 64, 32), 256, SP_SMEM>>>(
        Sgm, Wgt, gsu_b, gsu_bn_p, Y3, C_DIM, M_DIM / 32);

    // 9+10) fused final double-LIF
    lif_final_kernel<<<lif_blocks, 256>>>(Y3, Y2, (float*)d_out);
}

// round 15
// speedup vs baseline: 1.6367x; 1.6367x over previous
#include <cuda_runtime.h>
#include <cuda_bf16.h>
#include <math.h>

#define T_DIM 128
#define B_DIM 64
#define C_DIM 768
#define M_DIM (T_DIM * B_DIM)   // 8192
#define K_DW  31
#define EPSF  1e-5f

typedef unsigned long long ull;
typedef unsigned int uint32;
typedef unsigned short ushort;

// ---------------- scratch ----------------
__device__ float g_Y1 [M_DIM * C_DIM];
__device__ float g_Y2 [M_DIM * 2 * C_DIM];
__device__ float g_Y3 [M_DIM * C_DIM];
__device__ char  g_S2i[M_DIM * C_DIM];           // spikes s8 (dw path)
__device__ char  g_Sgi[M_DIM * C_DIM];           // gate spikes s8
__device__ char  g_W2d[4][2 * C_DIM * C_DIM];    // W2 digits
__device__ char  g_Wgd[4][C_DIM * C_DIM];        // Wg digits
__device__ float g_D2 [2 * C_DIM];               // per-row scales
__device__ float g_Dg [C_DIM];
__device__ __nv_bfloat16 g_Hh[M_DIM * C_DIM];
__device__ __nv_bfloat16 g_Hm[M_DIM * C_DIM];
__device__ __nv_bfloat16 g_Hl[M_DIM * C_DIM];
__device__ __nv_bfloat16 g_W1hi[C_DIM * C_DIM];
__device__ __nv_bfloat16 g_W1mi[C_DIM * C_DIM];
__device__ __nv_bfloat16 g_W1lo[C_DIM * C_DIM];

// ---------------- helpers ----------------
__device__ __forceinline__ void mma_bf16(float* c, const uint32* a, uint32 b0, uint32 b1) {
    asm volatile(
        "mma.sync.aligned.m16n8k16.row.col.f32.bf16.bf16.f32 "
        "{%0,%1,%2,%3}, {%4,%5,%6,%7}, {%8,%9}, {%0,%1,%2,%3};"
        : "+f"(c[0]), "+f"(c[1]), "+f"(c[2]), "+f"(c[3])
        : "r"(a[0]), "r"(a[1]), "r"(a[2]), "r"(a[3]), "r"(b0), "r"(b1));
}
__device__ __forceinline__ void mma_s8(int* c, const uint32* a, uint32 b0, uint32 b1) {
    asm volatile(
        "mma.sync.aligned.m16n8k32.row.col.s32.s8.s8.s32 "
        "{%0,%1,%2,%3}, {%4,%5,%6,%7}, {%8,%9}, {%0,%1,%2,%3};"
        : "+r"(c[0]), "+r"(c[1]), "+r"(c[2]), "+r"(c[3])
        : "r"(a[0]), "r"(a[1]), "r"(a[2]), "r"(a[3]), "r"(b0), "r"(b1));
}
__device__ __forceinline__ void ldsm4(uint32* r, uint32 saddr) {
    asm volatile("ldmatrix.sync.aligned.m8n8.x4.shared.b16 {%0,%1,%2,%3}, [%4];"
        : "=r"(r[0]), "=r"(r[1]), "=r"(r[2]), "=r"(r[3]) : "r"(saddr));
}
#define CP16(dst, src) \
    asm volatile("cp.async.cg.shared.global [%0], [%1], 16;" :: "r"(dst), "l"(src))
#define CP_COMMIT() asm volatile("cp.async.commit_group;" ::: "memory")
#define CP_WAIT1()  asm volatile("cp.async.wait_group 1;" ::: "memory")

// ---------------- weight split (W1) ----------------
__global__ void __launch_bounds__(256) split_w_kernel(
    const float* __restrict__ W,
    __nv_bfloat16* __restrict__ hi, __nv_bfloat16* __restrict__ mi,
    __nv_bfloat16* __restrict__ lo, int n)
{
    int i = blockIdx.x * blockDim.x + threadIdx.x;
    if (i >= n) return;
    float w = W[i];
    __nv_bfloat16 h = __float2bfloat16(w);
    float r1 = w - __bfloat162float(h);
    __nv_bfloat16 m = __float2bfloat16(r1);
    float r2 = r1 - __bfloat162float(m);
    hi[i] = h; mi[i] = m; lo[i] = __float2bfloat16(r2);
}

// ---------------- 4-digit base-128 decomposition, per output row -------------
// w[row][k] = D_row * (q1/128 + q2/128^2 + q3/128^3 + q4/128^4) + eps,
// |eps| <= 2^-29 * D_row.  D_row = 2^(e+1) power of two -> all steps exact.
__global__ void __launch_bounds__(256) digit_kernel(
    const float* __restrict__ W,
    char* __restrict__ d0, char* __restrict__ d1,
    char* __restrict__ d2, char* __restrict__ d3,
    float* __restrict__ Dsc, int N, int K)
{
    int row = blockIdx.x * 8 + (threadIdx.x >> 5);
    int lane = threadIdx.x & 31;
    if (row >= N) return;
    const float* wr = W + (size_t)row * K;

    float mx = 0.0f;
    for (int k = lane; k < K; k += 32) mx = fmaxf(mx, fabsf(wr[k]));
    #pragma unroll
    for (int o = 16; o > 0; o >>= 1) mx = fmaxf(mx, __shfl_xor_sync(0xffffffffu, mx, o));

    int e; frexpf(mx, &e);                 // mx = m*2^e, m in [0.5,1)
    float D = exp2f((float)(e + 1));       // |w|/D < 0.5
    float inv = 1.0f / D;                  // exact
    if (lane == 0) Dsc[row] = D;

    for (int k = lane; k < K; k += 32) {
        float f = wr[k] * inv;
        f *= 128.0f; float q1 = rintf(f); f -= q1;
        f *= 128.0f; float q2 = rintf(f); f -= q2;
        f *= 128.0f; float q3 = rintf(f); f -= q3;
        f *= 128.0f; float q4 = rintf(f);
        size_t idx = (size_t)row * K + k;
        d0[idx] = (char)(int)q1; d1[idx] = (char)(int)q2;
        d2[idx] = (char)(int)q3; d3[idx] = (char)(int)q4;
    }
}

// ---------------- block reduction helper ----------------
__inline__ __device__ float block_reduce_sum(float val, float* shmem) {
    int tid = threadIdx.x;
    #pragma unroll
    for (int o = 16; o > 0; o >>= 1) val += __shfl_xor_sync(0xffffffffu, val, o);
    if ((tid & 31) == 0) shmem[tid >> 5] = val;
    __syncthreads();
    float r = 0.0f;
    if (tid < 8) r = shmem[tid];
    if (tid < 32) {
        #pragma unroll
        for (int o = 4; o > 0; o >>= 1) r += __shfl_xor_sync(0xffffffffu, r, o);
    }
    if (tid == 0) shmem[0] = r;
    __syncthreads();
    r = shmem[0];
    __syncthreads();
    return r;
}

// ---------------- layernorm -> 3-way bf16 split output ----------------
__global__ void __launch_bounds__(256) ln_kernel(
    const float* __restrict__ x, const float* __restrict__ gam,
    const float* __restrict__ bet,
    __nv_bfloat16* __restrict__ Hh, __nv_bfloat16* __restrict__ Hm,
    __nv_bfloat16* __restrict__ Hl)
{
    __shared__ float red[32];
    int row = blockIdx.x;
    const float* xr = x + (size_t)row * C_DIM;
    int tid = threadIdx.x;

    float lx[3];
    float s = 0.0f;
    #pragma unroll
    for (int i = 0; i < 3; i++) { lx[i] = xr[tid + i * 256]; s += lx[i]; }
    float mean = block_reduce_sum(s, red) * (1.0f / C_DIM);

    float s2 = 0.0f;
    #pragma unroll
    for (int i = 0; i < 3; i++) { float d = lx[i] - mean; s2 += d * d; }
    float var = block_reduce_sum(s2, red) * (1.0f / C_DIM);
    float rstd = 1.0f / sqrtf(var + EPSF);

    #pragma unroll
    for (int i = 0; i < 3; i++) {
        int c = tid + i * 256;
        float y = (lx[i] - mean) * rstd * gam[c] + bet[c];
        __nv_bfloat16 h = __float2bfloat16(y);
        float r1 = y - __bfloat162float(h);
        __nv_bfloat16 m = __float2bfloat16(r1);
        float r2 = r1 - __bfloat162float(m);
        size_t idx = (size_t)row * C_DIM + c;
        Hh[idx] = h; Hm[idx] = m; Hl[idx] = __float2bfloat16(r2);
    }
}

// ================= dense GEMM1 (6-term bf16 split, mma) =================
#define GBM 128
#define GBN 64
#define GBK 32
#define ASTR 40

#define S6_AH (GBM * ASTR)
#define S6_BH (GBN * ASTR)
#define S6_STG (3 * S6_AH + 3 * S6_BH)
#define S6_SMEM (2 * S6_STG * 2)

__global__ void __launch_bounds__(256) gemm_split6_bf16(
    const __nv_bfloat16* __restrict__ Ah, const __nv_bfloat16* __restrict__ Am,
    const __nv_bfloat16* __restrict__ Al,
    const __nv_bfloat16* __restrict__ Wh, const __nv_bfloat16* __restrict__ Wm,
    const __nv_bfloat16* __restrict__ Wl,
    const float* __restrict__ bias, const float* __restrict__ bnp,
    float* __restrict__ Out, int M, int N, int K)
{
    extern __shared__ __align__(16) unsigned short sm[];
    uint32 smb = (uint32)__cvta_generic_to_shared(sm);

    int tid = threadIdx.x;
    int wid = tid >> 5, lane = tid & 31;
    int wm = wid & 3, wn = wid >> 2;
    int bn0 = blockIdx.x * GBN, bm0 = blockIdx.y * GBM;

    int ldrow = tid >> 2;
    int ldcol = (tid & 3) * 8;

    const __nv_bfloat16* Asel[3] = {Ah, Am, Al};
    const __nv_bfloat16* Wsel[3] = {Wh, Wm, Wl};

    float acc[2][4][4];
    #pragma unroll
    for (int mt = 0; mt < 2; mt++)
        #pragma unroll
        for (int nt = 0; nt < 4; nt++)
            #pragma unroll
            for (int q = 0; q < 4; q++) acc[mt][nt][q] = 0.0f;

    int a_row = (lane & 7) + ((lane >> 3) & 1) * 8;
    int a_ko  = ((lane >> 4) & 1) * 8;
    int b_row = (lane & 7) + ((lane >> 4) & 1) * 8;
    int b_ko  = ((lane >> 3) & 1) * 8;

    auto issue = [&](int st, int k0) {
        #pragma unroll
        for (int s = 0; s < 3; s++) {
            #pragma unroll
            for (int j = 0; j < 2; j++) {
                int row = ldrow + j * 64;
                uint32 dst = smb + (uint32)(st * S6_STG + s * S6_AH + row * ASTR + ldcol) * 2;
                CP16(dst, Asel[s] + (size_t)(bm0 + row) * K + k0 + ldcol);
            }
            uint32 dst = smb + (uint32)(st * S6_STG + 3 * S6_AH + s * S6_BH + ldrow * ASTR + ldcol) * 2;
            CP16(dst, Wsel[s] + (size_t)(bn0 + ldrow) * K + k0 + ldcol);
        }
    };

    int NCH = K / GBK;
    issue(0, 0);
    CP_COMMIT();

    for (int ch = 0; ch < NCH; ch++) {
        if (ch + 1 < NCH) issue((ch + 1) & 1, (ch + 1) * GBK);
        CP_COMMIT();
        CP_WAIT1();
        __syncthreads();

        int st = ch & 1;
        uint32 abase = smb + (uint32)(st * S6_STG) * 2;
        uint32 bbase = smb + (uint32)(st * S6_STG + 3 * S6_AH) * 2;

        #pragma unroll
        for (int ks = 0; ks < 2; ks++) {
            int kc = ks * 16;
            uint32 af[3][2][4];
            #pragma unroll
            for (int s = 0; s < 3; s++)
                #pragma unroll
                for (int mt = 0; mt < 2; mt++)
                    ldsm4(af[s][mt], abase + (uint32)(s * S6_AH + (wm * 32 + mt * 16 + a_row) * ASTR + kc + a_ko) * 2);
            #pragma unroll
            for (int t = 0; t < 3; t++) {
                #pragma unroll
                for (int g = 0; g < 2; g++) {
                    uint32 bf[4];
                    ldsm4(bf, bbase + (uint32)(t * S6_BH + (wn * 32 + g * 16 + b_row) * ASTR + kc + b_ko) * 2);
                    #pragma unroll
                    for (int s = 0; s < 3; s++) {
                        if (s + t <= 2) {
                            mma_bf16(acc[0][2 * g],     af[s][0], bf[0], bf[1]);
                            mma_bf16(acc[1][2 * g],     af[s][1], bf[0], bf[1]);
                            mma_bf16(acc[0][2 * g + 1], af[s][0], bf[2], bf[3]);
                            mma_bf16(acc[1][2 * g + 1], af[s][1], bf[2], bf[3]);
                        }
                    }
                }
            }
        }
        __syncthreads();
    }

    int r4 = lane >> 2, c2 = (lane & 3) * 2;
    #pragma unroll
    for (int nt = 0; nt < 4; nt++) {
        int n0 = bn0 + wn * 32 + nt * 8 + c2;
        float g0 = bnp[n0],     be0 = bnp[N + n0],     mm0 = bnp[2*N + n0],     vv0 = bnp[3*N + n0];
        float g1 = bnp[n0 + 1], be1 = bnp[N + n0 + 1], mm1 = bnp[2*N + n0 + 1], vv1 = bnp[3*N + n0 + 1];
        float sc0 = g0 / sqrtf(vv0 + EPSF), sh0 = be0 - mm0 * sc0;
        float sc1 = g1 / sqrtf(vv1 + EPSF), sh1 = be1 - mm1 * sc1;
        float bs0 = bias[n0], bs1 = bias[n0 + 1];
        #pragma unroll
        for (int mt = 0; mt < 2; mt++) {
            int m0 = bm0 + wm * 32 + mt * 16 + r4;
            float2 o0, o1;
            o0.x = (acc[mt][nt][0] + bs0) * sc0 + sh0;
            o0.y = (acc[mt][nt][1] + bs1) * sc1 + sh1;
            o1.x = (acc[mt][nt][2] + bs0) * sc0 + sh0;
            o1.y = (acc[mt][nt][3] + bs1) * sc1 + sh1;
            *(float2*)&Out[(size_t)m0 * N + n0] = o0;
            *(float2*)&Out[(size_t)(m0 + 8) * N + n0] = o1;
        }
    }
}

// ================= int8 spike GEMM (4 digit passes) =================
// Out[m,n] = bn( D_n * sum_s 128^-(s+1) * (Σ_k spike*q_s) + bias )
#define I8_ASTR 80                       // bytes per smem row
#define I8_AH  (GBM * I8_ASTR)           // 10240
#define I8_BH  (GBN * I8_ASTR)           // 5120
#define I8_STG (I8_AH + I8_BH)           // 15360
#define I8_SMEM (2 * I8_STG)             // 30720

__global__ void __launch_bounds__(256) gemm_spike_i8(
    const char* __restrict__ A,
    const char* __restrict__ d0, const char* __restrict__ d1,
    const char* __restrict__ d2, const char* __restrict__ d3,
    const float* __restrict__ Dsc,
    const float* __restrict__ bias, const float* __restrict__ bnp,
    float* __restrict__ Out, int M, int N, int K)
{
    extern __shared__ __align__(16) char smi[];
    uint32 smb = (uint32)__cvta_generic_to_shared(smi);

    int tid = threadIdx.x;
    int wid = tid >> 5, lane = tid & 31;
    int wm = wid & 3, wn = wid >> 2;
    int bn0 = blockIdx.x * GBN, bm0 = blockIdx.y * GBM;

    const char* digs[4] = {d0, d1, d2, d3};

    float facc[2][4][4];
    #pragma unroll
    for (int mt = 0; mt < 2; mt++)
        #pragma unroll
        for (int nt = 0; nt < 4; nt++)
            #pragma unroll
            for (int q = 0; q < 4; q++) facc[mt][nt][q] = 0.0f;

    int a_row = (lane & 7) + ((lane >> 3) & 1) * 8;
    int a_kb  = ((lane >> 4) & 1) * 16;       // bytes
    int b_row = (lane & 7) + ((lane >> 4) & 1) * 8;
    int b_kb  = ((lane >> 3) & 1) * 16;

    int arow = tid >> 2, acg = (tid & 3) * 16;    // A: 2 loads/thread
    int brow = tid >> 2, bcg = (tid & 3) * 16;    // B: 1 load/thread

    #pragma unroll 1
    for (int s = 0; s < 4; s++) {
        const char* Bp = digs[s];
        int acc[2][4][4];
        #pragma unroll
        for (int mt = 0; mt < 2; mt++)
            #pragma unroll
            for (int nt = 0; nt < 4; nt++)
                #pragma unroll
                for (int q = 0; q < 4; q++) acc[mt][nt][q] = 0;

        auto issue = [&](int st, int k0) {
            #pragma unroll
            for (int j = 0; j < 2; j++) {
                int row = arow + j * 64;
                uint32 dst = smb + (uint32)(st * I8_STG + row * I8_ASTR + acg);
                CP16(dst, A + (size_t)(bm0 + row) * K + k0 + acg);
            }
            uint32 dst = smb + (uint32)(st * I8_STG + I8_AH + brow * I8_ASTR + bcg);
            CP16(dst, Bp + (size_t)(bn0 + brow) * K + k0 + bcg);
        };

        int NCH = K / 64;                 // 12 chunks of 64 s8
        issue(0, 0);
        CP_COMMIT();

        for (int ch = 0; ch < NCH; ch++) {
            if (ch + 1 < NCH) issue((ch + 1) & 1, (ch + 1) * 64);
            CP_COMMIT();
            CP_WAIT1();
            __syncthreads();

            int st = ch & 1;
            uint32 abase = smb + (uint32)(st * I8_STG);
            uint32 bbase = smb + (uint32)(st * I8_STG + I8_AH);

            #pragma unroll
            for (int ks = 0; ks < 2; ks++) {
                int kc = ks * 32;         // bytes
                uint32 af[2][4];
                #pragma unroll
                for (int mt = 0; mt < 2; mt++)
                    ldsm4(af[mt], abase + (uint32)((wm * 32 + mt * 16 + a_row) * I8_ASTR + kc + a_kb));
                #pragma unroll
                for (int g = 0; g < 2; g++) {
                    uint32 bf[4];
                    ldsm4(bf, bbase + (uint32)((wn * 32 + g * 16 + b_row) * I8_ASTR + kc + b_kb));
                    mma_s8(acc[0][2 * g],     af[0], bf[0], bf[1]);
                    mma_s8(acc[1][2 * g],     af[1], bf[0], bf[1]);
                    mma_s8(acc[0][2 * g + 1], af[0], bf[2], bf[3]);
                    mma_s8(acc[1][2 * g + 1], af[1], bf[2], bf[3]);
                }
            }
            __syncthreads();
        }

        // combine: exact power-of-two scaling
        float psc = exp2f(-7.0f * (float)(s + 1));
        int c2l = (lane & 3) * 2;
        #pragma unroll
        for (int nt = 0; nt < 4; nt++) {
            int n0 = bn0 + wn * 32 + nt * 8 + c2l;
            float c0 = Dsc[n0] * psc;
            float c1 = Dsc[n0 + 1] * psc;
            #pragma unroll
            for (int mt = 0; mt < 2; mt++) {
                facc[mt][nt][0] += c0 * (float)acc[mt][nt][0];
                facc[mt][nt][1] += c1 * (float)acc[mt][nt][1];
                facc[mt][nt][2] += c0 * (float)acc[mt][nt][2];
                facc[mt][nt][3] += c1 * (float)acc[mt][nt][3];
            }
        }
    }

    int r4 = lane >> 2, c2 = (lane & 3) * 2;
    #pragma unroll
    for (int nt = 0; nt < 4; nt++) {
        int n0 = bn0 + wn * 32 + nt * 8 + c2;
        float g0 = bnp[n0],     be0 = bnp[N + n0],     mm0 = bnp[2*N + n0],     vv0 = bnp[3*N + n0];
        float g1 = bnp[n0 + 1], be1 = bnp[N + n0 + 1], mm1 = bnp[2*N + n0 + 1], vv1 = bnp[3*N + n0 + 1];
        float sc0 = g0 / sqrtf(vv0 + EPSF), sh0 = be0 - mm0 * sc0;
        float sc1 = g1 / sqrtf(vv1 + EPSF), sh1 = be1 - mm1 * sc1;
        float bs0 = bias[n0], bs1 = bias[n0 + 1];
        #pragma unroll
        for (int mt = 0; mt < 2; mt++) {
            int m0 = bm0 + wm * 32 + mt * 16 + r4;
            float2 o0, o1;
            o0.x = (facc[mt][nt][0] + bs0) * sc0 + sh0;
            o0.y = (facc[mt][nt][1] + bs1) * sc1 + sh1;
            o1.x = (facc[mt][nt][2] + bs0) * sc0 + sh0;
            o1.y = (facc[mt][nt][3] + bs1) * sc1 + sh1;
            *(float2*)&Out[(size_t)m0 * N + n0] = o0;
            *(float2*)&Out[(size_t)(m0 + 8) * N + n0] = o1;
        }
    }
}

// ---------------- fused lif1 -> depthwise -> bn2+lif2 -> s8 spikes -----------
#define DW_PAD 15
#define LD_SXP_ROWS (T_DIM + 2 * DW_PAD)
#define LIFDW_SMEM (LD_SXP_ROWS * 64 * 4 + T_DIM * 64 * 4)

__global__ void __launch_bounds__(256) lifdw_kernel(
    const float* __restrict__ Y1, const float* __restrict__ w,
    const float* __restrict__ bvec, const float* __restrict__ bn2p,
    char* __restrict__ S2i)
{
    extern __shared__ __align__(16) char smraw[];
    float (*sxp)[64] = (float(*)[64])smraw;
    float (*sd)[64]  = (float(*)[64])(smraw + LD_SXP_ROWS * 64 * 4);

    int b  = blockIdx.x;
    int c0 = blockIdx.y * 64;
    int tid = threadIdx.x;

    for (int i = tid; i < 2 * DW_PAD * 64; i += 256) {
        int r = i >> 6, ci = i & 63;
        if (r < DW_PAD) sxp[r][ci] = 0.0f;
        else            sxp[T_DIM + DW_PAD + (r - DW_PAD)][ci] = 0.0f;
    }
    for (int i = tid; i < T_DIM * 64; i += 256) {
        int t = i >> 6, ci = i & 63;
        sxp[t + DW_PAD][ci] = Y1[((size_t)t * B_DIM + b) * C_DIM + c0 + ci];
    }
    __syncthreads();

    if (tid < 64) {
        float v = 0.0f;
        #pragma unroll 4
        for (int t = 0; t < T_DIM; t++) {
            v = v * 0.5f + sxp[t + DW_PAD][tid];
            float s = (v >= 1.0f) ? 1.0f : 0.0f;
            v = (s > 0.0f) ? 0.0f : v;
            sxp[t + DW_PAD][tid] = s;
        }
    }
    __syncthreads();

    {
        int ci = tid & 63;
        int tg = tid >> 6;
        int c  = c0 + ci;
        int t0 = tg * 32;

        float wr[K_DW];
        #pragma unroll
        for (int k = 0; k < K_DW; k++) wr[k] = w[c * K_DW + k];
        float bb = bvec[c];

        float acc[32];
        #pragma unroll
        for (int i = 0; i < 32; i++) acc[i] = bb;

        #pragma unroll
        for (int dt = -DW_PAD; dt <= 31 + DW_PAD; dt++) {
            float sv = sxp[t0 + dt + DW_PAD][ci];
            #pragma unroll
            for (int i = 0; i < 32; i++) {
                int k = dt - i + DW_PAD;
                if (k >= 0 && k < K_DW) acc[i] += sv * wr[k];
            }
        }
        __syncthreads();
        #pragma unroll
        for (int i = 0; i < 32; i++) sd[t0 + i][ci] = acc[i];
    }
    __syncthreads();

    char* sout = (char*)smraw;
    if (tid < 64) {
        int c = c0 + tid;
        float g = bn2p[c], be = bn2p[C_DIM + c], mm = bn2p[2 * C_DIM + c], vv = bn2p[3 * C_DIM + c];
        float sc = g / sqrtf(vv + EPSF);
        float sh = be - mm * sc;
        float v = 0.0f;
        #pragma unroll 4
        for (int t = 0; t < T_DIM; t++) {
            float xv = sd[t][tid] * sc + sh;
            v = v * 0.5f + xv;
            float s = (v >= 1.0f) ? 1.0f : 0.0f;
            v = (s > 0.0f) ? 0.0f : v;
            sout[t * 64 + tid] = (char)(s > 0.0f ? 1 : 0);
        }
    }
    __syncthreads();

    for (int i = tid; i < T_DIM * 64; i += 256) {
        int t = i >> 6, ci = i & 63;
        S2i[((size_t)t * B_DIM + b) * C_DIM + c0 + ci] = sout[t * 64 + ci];
    }
}

// ---------------- gate LIF -> s8 spikes ----------------
__global__ void __launch_bounds__(384) gate_kernel(
    const float* __restrict__ Y2, char* __restrict__ Sgi)
{
    int b = blockIdx.x;
    int c = blockIdx.y * 384 + threadIdx.x;
    const float* xp = Y2 + (size_t)b * 2 * C_DIM + C_DIM + c;
    size_t stx = (size_t)B_DIM * 2 * C_DIM;

    float v = 0.0f;
    #pragma unroll 4
    for (int t = 0; t < T_DIM; t++) {
        float xv = xp[(size_t)t * stx];
        v = v * 0.5f + xv;
        float s = (v >= 1.0f) ? 1.0f : 0.0f;
        v = (s > 0.0f) ? 0.0f : v;
        Sgi[((size_t)t * B_DIM + b) * C_DIM + c] = (char)(s > 0.0f ? 1 : 0);
    }
}

// ---------------- fused final double-LIF ----------------
__global__ void __launch_bounds__(256) lif_final_kernel(
    const float* __restrict__ Y3, const float* __restrict__ Y2out,
    float* __restrict__ Out)
{
    int j = blockIdx.x * blockDim.x + threadIdx.x;
    if (j >= B_DIM * C_DIM) return;
    int b = j / C_DIM, c = j % C_DIM;
    const float* yp = Y3 + (size_t)b * C_DIM + c;
    const float* op = Y2out + (size_t)b * 2 * C_DIM + c;
    float* sp = Out + (size_t)j;
    size_t st3 = (size_t)B_DIM * C_DIM;
    size_t st2 = (size_t)B_DIM * 2 * C_DIM;

    float v9 = 0.0f, v10 = 0.0f;
    #pragma unroll 4
    for (int t = 0; t < T_DIM; t++) {
        float g = yp[(size_t)t * st3];
        v9 = v9 * 0.5f + g;
        float s9 = (v9 >= 1.0f) ? 1.0f : 0.0f;
        v9 = (s9 > 0.0f) ? 0.0f : v9;
        float x = op[(size_t)t * st2] * s9;
        v10 = v10 * 0.5f + x;
        float s10 = (v10 >= 1.0f) ? 1.0f : 0.0f;
        v10 = (s10 > 0.0f) ? 0.0f : v10;
        sp[(size_t)t * st3] = s10;
    }
}

// ---------------- launch ----------------
extern "C" void kernel_launch(void* const* d_in, const int* in_sizes, int n_in,
                              void* d_out, int out_size)
{
    const float* x        = (const float*)d_in[0];
    const float* ln_g     = (const float*)d_in[1];
    const float* ln_b     = (const float*)d_in[2];
    const float* pw1_w    = (const float*)d_in[3];
    const float* pw1_b    = (const float*)d_in[4];
    const float* bn1_p    = (const float*)d_in[5];
    const float* dw_w     = (const float*)d_in[6];
    const float* dw_b     = (const float*)d_in[7];
    const float* bn2_p    = (const float*)d_in[8];
    const float* pw2_w    = (const float*)d_in[9];
    const float* pw2_b    = (const float*)d_in[10];
    const float* bn3_p    = (const float*)d_in[11];
    const float* gsu_w    = (const float*)d_in[12];
    const float* gsu_b    = (const float*)d_in[13];
    const float* gsu_bn_p = (const float*)d_in[14];

    float *Y1, *Y2, *Y3, *D2, *Dg;
    char *S2i, *Sgi, *W2d0, *W2d1, *W2d2, *W2d3, *Wgd0, *Wgd1, *Wgd2, *Wgd3;
    __nv_bfloat16 *Hh, *Hm, *Hl, *W1hi, *W1mi, *W1lo;
    cudaGetSymbolAddress((void**)&Y1,   g_Y1);
    cudaGetSymbolAddress((void**)&Y2,   g_Y2);
    cudaGetSymbolAddress((void**)&Y3,   g_Y3);
    cudaGetSymbolAddress((void**)&S2i,  g_S2i);
    cudaGetSymbolAddress((void**)&Sgi,  g_Sgi);
    cudaGetSymbolAddress((void**)&D2,   g_D2);
    cudaGetSymbolAddress((void**)&Dg,   g_Dg);
    cudaGetSymbolAddress((void**)&Hh,   g_Hh);
    cudaGetSymbolAddress((void**)&Hm,   g_Hm);
    cudaGetSymbolAddress((void**)&Hl,   g_Hl);
    cudaGetSymbolAddress((void**)&W1hi, g_W1hi);
    cudaGetSymbolAddress((void**)&W1mi, g_W1mi);
    cudaGetSymbolAddress((void**)&W1lo, g_W1lo);
    char* base2; cudaGetSymbolAddress((void**)&base2, g_W2d);
    W2d0 = base2; W2d1 = base2 + (size_t)2*C_DIM*C_DIM;
    W2d2 = base2 + (size_t)4*C_DIM*C_DIM; W2d3 = base2 + (size_t)6*C_DIM*C_DIM;
    char* baseg; cudaGetSymbolAddress((void**)&baseg, g_Wgd);
    Wgd0 = baseg; Wgd1 = baseg + (size_t)C_DIM*C_DIM;
    Wgd2 = baseg + (size_t)2*C_DIM*C_DIM; Wgd3 = baseg + (size_t)3*C_DIM*C_DIM;

    cudaFuncSetAttribute(gemm_split6_bf16,
        cudaFuncAttributeMaxDynamicSharedMemorySize, S6_SMEM);
    cudaFuncSetAttribute(gemm_spike_i8,
        cudaFuncAttributeMaxDynamicSharedMemorySize, I8_SMEM);
    cudaFuncSetAttribute(lifdw_kernel,
        cudaFuncAttributeMaxDynamicSharedMemorySize, LIFDW_SMEM);

    const int lif_blocks = (B_DIM * C_DIM + 255) / 256;   // 192

    // 0) W1 split + W2/Wg digit decompositions
    split_w_kernel<<<(C_DIM * C_DIM + 255) / 256, 256>>>(pw1_w, W1hi, W1mi, W1lo, C_DIM * C_DIM);
    digit_kernel<<<(2 * C_DIM + 7) / 8, 256>>>(pw2_w, W2d0, W2d1, W2d2, W2d3, D2, 2 * C_DIM, C_DIM);
    digit_kernel<<<(C_DIM + 7) / 8, 256>>>(gsu_w, Wgd0, Wgd1, Wgd2, Wgd3, Dg, C_DIM, C_DIM);

    // 1) LayerNorm -> H splits
    ln_kernel<<<M_DIM, 256>>>(x, ln_g, ln_b, Hh, Hm, Hl);

    // 2) pw1 + bias + bn1 (dense bf16 6-term mma)
    gemm_split6_bf16<<<dim3(C_DIM / GBN, M_DIM / GBM), 256, S6_SMEM>>>(
        Hh, Hm, Hl, W1hi, W1mi, W1lo, pw1_b, bn1_p, Y1, M_DIM, C_DIM, C_DIM);

    // 3-5) fused: lif1 -> depthwise -> bn2+lif2 -> s8 spikes
    lifdw_kernel<<<dim3(B_DIM, C_DIM / 64), 256, LIFDW_SMEM>>>(
        Y1, dw_w, dw_b, bn2_p, S2i);

    // 6) pw2 + bias + bn3 (int8 4-digit mma)
    gemm_spike_i8<<<dim3(2 * C_DIM / GBN, M_DIM / GBM), 256, I8_SMEM>>>(
        S2i, W2d0, W2d1, W2d2, W2d3, D2, pw2_b, bn3_p, Y2, M_DIM, 2 * C_DIM, C_DIM);

    // 7) gate LIF -> s8 spikes
    gate_kernel<<<dim3(B_DIM, 2), 384>>>(Y2, Sgi);

    // 8) gsu GEMM (int8 4-digit mma)
    gemm_spike_i8<<<dim3(C_DIM / GBN, M_DIM / GBM), 256, I8_SMEM>>>(
        Sgi, Wgd0, Wgd1, Wgd2, Wgd3, Dg, gsu_b, gsu_bn_p, Y3, M_DIM, C_DIM, C_DIM);

    // 9+10) fused final double-LIF
    lif_final_kernel<<<lif_blocks, 256>>>(Y3, Y2, (float*)d_out);
}

// round 16
// speedup vs baseline: 1.7236x; 1.0531x over previous
#include <cuda_runtime.h>
#include <cuda_bf16.h>
#include <math.h>

#define T_DIM 128
#define B_DIM 64
#define C_DIM 768
#define M_DIM (T_DIM * B_DIM)   // 8192
#define K_DW  31
#define EPSF  1e-5f

typedef unsigned long long ull;
typedef unsigned int uint32;
typedef unsigned short ushort;

// ---------------- scratch ----------------
__device__ float g_Y1 [M_DIM * C_DIM];
__device__ float g_Y2 [M_DIM * 2 * C_DIM];
__device__ float g_Y3 [M_DIM * C_DIM];
__device__ char  g_S2i[M_DIM * C_DIM];           // spikes s8 (dw path)
__device__ char  g_Sgi[M_DIM * C_DIM];           // gate spikes s8
__device__ char  g_W2d[4][2 * C_DIM * C_DIM];    // W2 digits
__device__ char  g_Wgd[4][C_DIM * C_DIM];        // Wg digits
__device__ float g_D2 [2 * C_DIM];               // per-row scales
__device__ float g_Dg [C_DIM];
__device__ __nv_bfloat16 g_Hh[M_DIM * C_DIM];
__device__ __nv_bfloat16 g_Hm[M_DIM * C_DIM];
__device__ __nv_bfloat16 g_Hl[M_DIM * C_DIM];
__device__ __nv_bfloat16 g_W1hi[C_DIM * C_DIM];
__device__ __nv_bfloat16 g_W1mi[C_DIM * C_DIM];
__device__ __nv_bfloat16 g_W1lo[C_DIM * C_DIM];

// ---------------- helpers ----------------
__device__ __forceinline__ void mma_bf16(float* c, const uint32* a, uint32 b0, uint32 b1) {
    asm volatile(
        "mma.sync.aligned.m16n8k16.row.col.f32.bf16.bf16.f32 "
        "{%0,%1,%2,%3}, {%4,%5,%6,%7}, {%8,%9}, {%0,%1,%2,%3};"
        : "+f"(c[0]), "+f"(c[1]), "+f"(c[2]), "+f"(c[3])
        : "r"(a[0]), "r"(a[1]), "r"(a[2]), "r"(a[3]), "r"(b0), "r"(b1));
}
__device__ __forceinline__ void mma_s8(int* c, const uint32* a, uint32 b0, uint32 b1) {
    asm volatile(
        "mma.sync.aligned.m16n8k32.row.col.s32.s8.s8.s32 "
        "{%0,%1,%2,%3}, {%4,%5,%6,%7}, {%8,%9}, {%0,%1,%2,%3};"
        : "+r"(c[0]), "+r"(c[1]), "+r"(c[2]), "+r"(c[3])
        : "r"(a[0]), "r"(a[1]), "r"(a[2]), "r"(a[3]), "r"(b0), "r"(b1));
}
__device__ __forceinline__ void ldsm4(uint32* r, uint32 saddr) {
    asm volatile("ldmatrix.sync.aligned.m8n8.x4.shared.b16 {%0,%1,%2,%3}, [%4];"
        : "=r"(r[0]), "=r"(r[1]), "=r"(r[2]), "=r"(r[3]) : "r"(saddr));
}
#define CP16(dst, src) \
    asm volatile("cp.async.cg.shared.global [%0], [%1], 16;" :: "r"(dst), "l"(src))
#define CP_COMMIT() asm volatile("cp.async.commit_group;" ::: "memory")
#define CP_WAIT1()  asm volatile("cp.async.wait_group 1;" ::: "memory")

// ---------------- weight split (W1) ----------------
__global__ void __launch_bounds__(256) split_w_kernel(
    const float* __restrict__ W,
    __nv_bfloat16* __restrict__ hi, __nv_bfloat16* __restrict__ mi,
    __nv_bfloat16* __restrict__ lo, int n)
{
    int i = blockIdx.x * blockDim.x + threadIdx.x;
    if (i >= n) return;
    float w = W[i];
    __nv_bfloat16 h = __float2bfloat16(w);
    float r1 = w - __bfloat162float(h);
    __nv_bfloat16 m = __float2bfloat16(r1);
    float r2 = r1 - __bfloat162float(m);
    hi[i] = h; mi[i] = m; lo[i] = __float2bfloat16(r2);
}

// ---------------- 4-digit base-128 decomposition, per output row -------------
__global__ void __launch_bounds__(256) digit_kernel(
    const float* __restrict__ W,
    char* __restrict__ d0, char* __restrict__ d1,
    char* __restrict__ d2, char* __restrict__ d3,
    float* __restrict__ Dsc, int N, int K)
{
    int row = blockIdx.x * 8 + (threadIdx.x >> 5);
    int lane = threadIdx.x & 31;
    if (row >= N) return;
    const float* wr = W + (size_t)row * K;

    float mx = 0.0f;
    for (int k = lane; k < K; k += 32) mx = fmaxf(mx, fabsf(wr[k]));
    #pragma unroll
    for (int o = 16; o > 0; o >>= 1) mx = fmaxf(mx, __shfl_xor_sync(0xffffffffu, mx, o));

    int e; frexpf(mx, &e);
    float D = exp2f((float)(e + 1));
    float inv = 1.0f / D;
    if (lane == 0) Dsc[row] = D;

    for (int k = lane; k < K; k += 32) {
        float f = wr[k] * inv;
        f *= 128.0f; float q1 = rintf(f); f -= q1;
        f *= 128.0f; float q2 = rintf(f); f -= q2;
        f *= 128.0f; float q3 = rintf(f); f -= q3;
        f *= 128.0f; float q4 = rintf(f);
        size_t idx = (size_t)row * K + k;
        d0[idx] = (char)(int)q1; d1[idx] = (char)(int)q2;
        d2[idx] = (char)(int)q3; d3[idx] = (char)(int)q4;
    }
}

// ---------------- block reduction helper ----------------
__inline__ __device__ float block_reduce_sum(float val, float* shmem) {
    int tid = threadIdx.x;
    #pragma unroll
    for (int o = 16; o > 0; o >>= 1) val += __shfl_xor_sync(0xffffffffu, val, o);
    if ((tid & 31) == 0) shmem[tid >> 5] = val;
    __syncthreads();
    float r = 0.0f;
    if (tid < 8) r = shmem[tid];
    if (tid < 32) {
        #pragma unroll
        for (int o = 4; o > 0; o >>= 1) r += __shfl_xor_sync(0xffffffffu, r, o);
    }
    if (tid == 0) shmem[0] = r;
    __syncthreads();
    r = shmem[0];
    __syncthreads();
    return r;
}

// ---------------- layernorm -> 3-way bf16 split output ----------------
__global__ void __launch_bounds__(256) ln_kernel(
    const float* __restrict__ x, const float* __restrict__ gam,
    const float* __restrict__ bet,
    __nv_bfloat16* __restrict__ Hh, __nv_bfloat16* __restrict__ Hm,
    __nv_bfloat16* __restrict__ Hl)
{
    __shared__ float red[32];
    int row = blockIdx.x;
    const float* xr = x + (size_t)row * C_DIM;
    int tid = threadIdx.x;

    float lx[3];
    float s = 0.0f;
    #pragma unroll
    for (int i = 0; i < 3; i++) { lx[i] = xr[tid + i * 256]; s += lx[i]; }
    float mean = block_reduce_sum(s, red) * (1.0f / C_DIM);

    float s2 = 0.0f;
    #pragma unroll
    for (int i = 0; i < 3; i++) { float d = lx[i] - mean; s2 += d * d; }
    float var = block_reduce_sum(s2, red) * (1.0f / C_DIM);
    float rstd = 1.0f / sqrtf(var + EPSF);

    #pragma unroll
    for (int i = 0; i < 3; i++) {
        int c = tid + i * 256;
        float y = (lx[i] - mean) * rstd * gam[c] + bet[c];
        __nv_bfloat16 h = __float2bfloat16(y);
        float r1 = y - __bfloat162float(h);
        __nv_bfloat16 m = __float2bfloat16(r1);
        float r2 = r1 - __bfloat162float(m);
        size_t idx = (size_t)row * C_DIM + c;
        Hh[idx] = h; Hm[idx] = m; Hl[idx] = __float2bfloat16(r2);
    }
}

// ================= dense GEMM1 (6-term bf16 split, mma) =================
#define GBM 128
#define GBN 64
#define GBK 32
#define ASTR 40

#define S6_AH (GBM * ASTR)
#define S6_BH (GBN * ASTR)
#define S6_STG (3 * S6_AH + 3 * S6_BH)
#define S6_SMEM (2 * S6_STG * 2)

__global__ void __launch_bounds__(256) gemm_split6_bf16(
    const __nv_bfloat16* __restrict__ Ah, const __nv_bfloat16* __restrict__ Am,
    const __nv_bfloat16* __restrict__ Al,
    const __nv_bfloat16* __restrict__ Wh, const __nv_bfloat16* __restrict__ Wm,
    const __nv_bfloat16* __restrict__ Wl,
    const float* __restrict__ bias, const float* __restrict__ bnp,
    float* __restrict__ Out, int M, int N, int K)
{
    extern __shared__ __align__(16) unsigned short sm[];
    uint32 smb = (uint32)__cvta_generic_to_shared(sm);

    int tid = threadIdx.x;
    int wid = tid >> 5, lane = tid & 31;
    int wm = wid & 3, wn = wid >> 2;
    int bn0 = blockIdx.x * GBN, bm0 = blockIdx.y * GBM;

    int ldrow = tid >> 2;
    int ldcol = (tid & 3) * 8;

    const __nv_bfloat16* Asel[3] = {Ah, Am, Al};
    const __nv_bfloat16* Wsel[3] = {Wh, Wm, Wl};

    float acc[2][4][4];
    #pragma unroll
    for (int mt = 0; mt < 2; mt++)
        #pragma unroll
        for (int nt = 0; nt < 4; nt++)
            #pragma unroll
            for (int q = 0; q < 4; q++) acc[mt][nt][q] = 0.0f;

    int a_row = (lane & 7) + ((lane >> 3) & 1) * 8;
    int a_ko  = ((lane >> 4) & 1) * 8;
    int b_row = (lane & 7) + ((lane >> 4) & 1) * 8;
    int b_ko  = ((lane >> 3) & 1) * 8;

    auto issue = [&](int st, int k0) {
        #pragma unroll
        for (int s = 0; s < 3; s++) {
            #pragma unroll
            for (int j = 0; j < 2; j++) {
                int row = ldrow + j * 64;
                uint32 dst = smb + (uint32)(st * S6_STG + s * S6_AH + row * ASTR + ldcol) * 2;
                CP16(dst, Asel[s] + (size_t)(bm0 + row) * K + k0 + ldcol);
            }
            uint32 dst = smb + (uint32)(st * S6_STG + 3 * S6_AH + s * S6_BH + ldrow * ASTR + ldcol) * 2;
            CP16(dst, Wsel[s] + (size_t)(bn0 + ldrow) * K + k0 + ldcol);
        }
    };

    int NCH = K / GBK;
    issue(0, 0);
    CP_COMMIT();

    for (int ch = 0; ch < NCH; ch++) {
        if (ch + 1 < NCH) issue((ch + 1) & 1, (ch + 1) * GBK);
        CP_COMMIT();
        CP_WAIT1();
        __syncthreads();

        int st = ch & 1;
        uint32 abase = smb + (uint32)(st * S6_STG) * 2;
        uint32 bbase = smb + (uint32)(st * S6_STG + 3 * S6_AH) * 2;

        #pragma unroll
        for (int ks = 0; ks < 2; ks++) {
            int kc = ks * 16;
            uint32 af[3][2][4];
            #pragma unroll
            for (int s = 0; s < 3; s++)
                #pragma unroll
                for (int mt = 0; mt < 2; mt++)
                    ldsm4(af[s][mt], abase + (uint32)(s * S6_AH + (wm * 32 + mt * 16 + a_row) * ASTR + kc + a_ko) * 2);
            #pragma unroll
            for (int t = 0; t < 3; t++) {
                #pragma unroll
                for (int g = 0; g < 2; g++) {
                    uint32 bf[4];
                    ldsm4(bf, bbase + (uint32)(t * S6_BH + (wn * 32 + g * 16 + b_row) * ASTR + kc + b_ko) * 2);
                    #pragma unroll
                    for (int s = 0; s < 3; s++) {
                        if (s + t <= 2) {
                            mma_bf16(acc[0][2 * g],     af[s][0], bf[0], bf[1]);
                            mma_bf16(acc[1][2 * g],     af[s][1], bf[0], bf[1]);
                            mma_bf16(acc[0][2 * g + 1], af[s][0], bf[2], bf[3]);
                            mma_bf16(acc[1][2 * g + 1], af[s][1], bf[2], bf[3]);
                        }
                    }
                }
            }
        }
        __syncthreads();
    }

    int r4 = lane >> 2, c2 = (lane & 3) * 2;
    #pragma unroll
    for (int nt = 0; nt < 4; nt++) {
        int n0 = bn0 + wn * 32 + nt * 8 + c2;
        float g0 = bnp[n0],     be0 = bnp[N + n0],     mm0 = bnp[2*N + n0],     vv0 = bnp[3*N + n0];
        float g1 = bnp[n0 + 1], be1 = bnp[N + n0 + 1], mm1 = bnp[2*N + n0 + 1], vv1 = bnp[3*N + n0 + 1];
        float sc0 = g0 / sqrtf(vv0 + EPSF), sh0 = be0 - mm0 * sc0;
        float sc1 = g1 / sqrtf(vv1 + EPSF), sh1 = be1 - mm1 * sc1;
        float bs0 = bias[n0], bs1 = bias[n0 + 1];
        #pragma unroll
        for (int mt = 0; mt < 2; mt++) {
            int m0 = bm0 + wm * 32 + mt * 16 + r4;
            float2 o0, o1;
            o0.x = (acc[mt][nt][0] + bs0) * sc0 + sh0;
            o0.y = (acc[mt][nt][1] + bs1) * sc1 + sh1;
            o1.x = (acc[mt][nt][2] + bs0) * sc0 + sh0;
            o1.y = (acc[mt][nt][3] + bs1) * sc1 + sh1;
            *(float2*)&Out[(size_t)m0 * N + n0] = o0;
            *(float2*)&Out[(size_t)(m0 + 8) * N + n0] = o1;
        }
    }
}

// ================= int8 spike GEMM: SINGLE PASS, 4 digit B-streams ==========
// Out[m,n] = bn( D_n * sum_d 128^-(d+1) * (Σ_k spike*q_d) + bias )
#define I8_ASTR 80                       // bytes per smem row
#define I8_AH  (GBM * I8_ASTR)           // 10240
#define I8_BH  (GBN * I8_ASTR)           // 5120
#define I8_STG (I8_AH + 4 * I8_BH)       // 30720
#define I8_SMEM (2 * I8_STG)             // 61440

__global__ void __launch_bounds__(256) gemm_spike_i8(
    const char* __restrict__ A,
    const char* __restrict__ d0, const char* __restrict__ d1,
    const char* __restrict__ d2, const char* __restrict__ d3,
    const float* __restrict__ Dsc,
    const float* __restrict__ bias, const float* __restrict__ bnp,
    float* __restrict__ Out, int M, int N, int K)
{
    extern __shared__ __align__(16) char smi[];
    uint32 smb = (uint32)__cvta_generic_to_shared(smi);

    int tid = threadIdx.x;
    int wid = tid >> 5, lane = tid & 31;
    int wm = wid & 3, wn = wid >> 2;
    int bn0 = blockIdx.x * GBN, bm0 = blockIdx.y * GBM;

    const char* digs[4] = {d0, d1, d2, d3};

    int acc[4][2][4][4];
    #pragma unroll
    for (int d = 0; d < 4; d++)
        #pragma unroll
        for (int mt = 0; mt < 2; mt++)
            #pragma unroll
            for (int nt = 0; nt < 4; nt++)
                #pragma unroll
                for (int q = 0; q < 4; q++) acc[d][mt][nt][q] = 0;

    int a_row = (lane & 7) + ((lane >> 3) & 1) * 8;
    int a_kb  = ((lane >> 4) & 1) * 16;       // bytes
    int b_row = (lane & 7) + ((lane >> 4) & 1) * 8;
    int b_kb  = ((lane >> 3) & 1) * 16;

    int arow = tid >> 2, acg = (tid & 3) * 16;

    auto issue = [&](int st, int k0) {
        #pragma unroll
        for (int j = 0; j < 2; j++) {
            int row = arow + j * 64;
            uint32 dst = smb + (uint32)(st * I8_STG + row * I8_ASTR + acg);
            CP16(dst, A + (size_t)(bm0 + row) * K + k0 + acg);
        }
        #pragma unroll
        for (int d = 0; d < 4; d++) {
            uint32 dst = smb + (uint32)(st * I8_STG + I8_AH + d * I8_BH + arow * I8_ASTR + acg);
            CP16(dst, digs[d] + (size_t)(bn0 + arow) * K + k0 + acg);
        }
    };

    int NCH = K / 64;                 // 12 chunks of 64 s8
    issue(0, 0);
    CP_COMMIT();

    for (int ch = 0; ch < NCH; ch++) {
        if (ch + 1 < NCH) issue((ch + 1) & 1, (ch + 1) * 64);
        CP_COMMIT();
        CP_WAIT1();
        __syncthreads();

        int st = ch & 1;
        uint32 abase = smb + (uint32)(st * I8_STG);
        uint32 bbase = smb + (uint32)(st * I8_STG + I8_AH);

        #pragma unroll
        for (int ks = 0; ks < 2; ks++) {
            int kc = ks * 32;         // bytes
            uint32 af[2][4];
            #pragma unroll
            for (int mt = 0; mt < 2; mt++)
                ldsm4(af[mt], abase + (uint32)((wm * 32 + mt * 16 + a_row) * I8_ASTR + kc + a_kb));
            #pragma unroll
            for (int d = 0; d < 4; d++) {
                #pragma unroll
                for (int g = 0; g < 2; g++) {
                    uint32 bf[4];
                    ldsm4(bf, bbase + (uint32)(d * I8_BH + (wn * 32 + g * 16 + b_row) * I8_ASTR + kc + b_kb));
                    mma_s8(acc[d][0][2 * g],     af[0], bf[0], bf[1]);
                    mma_s8(acc[d][1][2 * g],     af[1], bf[0], bf[1]);
                    mma_s8(acc[d][0][2 * g + 1], af[0], bf[2], bf[3]);
                    mma_s8(acc[d][1][2 * g + 1], af[1], bf[2], bf[3]);
                }
            }
        }
        __syncthreads();
    }

    // epilogue: combine digits (order d0..d3, same as prior per-pass combine)
    int r4 = lane >> 2, c2 = (lane & 3) * 2;
    #pragma unroll
    for (int nt = 0; nt < 4; nt++) {
        int n0 = bn0 + wn * 32 + nt * 8 + c2;
        float facc[2][4];
        #pragma unroll
        for (int mt = 0; mt < 2; mt++)
            #pragma unroll
            for (int q = 0; q < 4; q++) facc[mt][q] = 0.0f;
        #pragma unroll
        for (int d = 0; d < 4; d++) {
            float psc = exp2f(-7.0f * (float)(d + 1));
            float c0 = Dsc[n0] * psc;
            float c1 = Dsc[n0 + 1] * psc;
            #pragma unroll
            for (int mt = 0; mt < 2; mt++) {
                facc[mt][0] += c0 * (float)acc[d][mt][nt][0];
                facc[mt][1] += c1 * (float)acc[d][mt][nt][1];
                facc[mt][2] += c0 * (float)acc[d][mt][nt][2];
                facc[mt][3] += c1 * (float)acc[d][mt][nt][3];
            }
        }
        float g0 = bnp[n0],     be0 = bnp[N + n0],     mm0 = bnp[2*N + n0],     vv0 = bnp[3*N + n0];
        float g1 = bnp[n0 + 1], be1 = bnp[N + n0 + 1], mm1 = bnp[2*N + n0 + 1], vv1 = bnp[3*N + n0 + 1];
        float sc0 = g0 / sqrtf(vv0 + EPSF), sh0 = be0 - mm0 * sc0;
        float sc1 = g1 / sqrtf(vv1 + EPSF), sh1 = be1 - mm1 * sc1;
        float bs0 = bias[n0], bs1 = bias[n0 + 1];
        #pragma unroll
        for (int mt = 0; mt < 2; mt++) {
            int m0 = bm0 + wm * 32 + mt * 16 + r4;
            float2 o0, o1;
            o0.x = (facc[mt][0] + bs0) * sc0 + sh0;
            o0.y = (facc[mt][1] + bs1) * sc1 + sh1;
            o1.x = (facc[mt][2] + bs0) * sc0 + sh0;
            o1.y = (facc[mt][3] + bs1) * sc1 + sh1;
            *(float2*)&Out[(size_t)m0 * N + n0] = o0;
            *(float2*)&Out[(size_t)(m0 + 8) * N + n0] = o1;
        }
    }
}

// ---------------- fused lif1 -> depthwise -> bn2+lif2 -> s8 spikes -----------
#define DW_PAD 15
#define LD_SXP_ROWS (T_DIM + 2 * DW_PAD)
#define LIFDW_SMEM (LD_SXP_ROWS * 64 * 4 + T_DIM * 64 * 4)

__global__ void __launch_bounds__(256) lifdw_kernel(
    const float* __restrict__ Y1, const float* __restrict__ w,
    const float* __restrict__ bvec, const float* __restrict__ bn2p,
    char* __restrict__ S2i)
{
    extern __shared__ __align__(16) char smraw[];
    float (*sxp)[64] = (float(*)[64])smraw;
    float (*sd)[64]  = (float(*)[64])(smraw + LD_SXP_ROWS * 64 * 4);

    int b  = blockIdx.x;
    int c0 = blockIdx.y * 64;
    int tid = threadIdx.x;

    for (int i = tid; i < 2 * DW_PAD * 64; i += 256) {
        int r = i >> 6, ci = i & 63;
        if (r < DW_PAD) sxp[r][ci] = 0.0f;
        else            sxp[T_DIM + DW_PAD + (r - DW_PAD)][ci] = 0.0f;
    }
    for (int i = tid; i < T_DIM * 64; i += 256) {
        int t = i >> 6, ci = i & 63;
        sxp[t + DW_PAD][ci] = Y1[((size_t)t * B_DIM + b) * C_DIM + c0 + ci];
    }
    __syncthreads();

    if (tid < 64) {
        float v = 0.0f;
        #pragma unroll 4
        for (int t = 0; t < T_DIM; t++) {
            v = v * 0.5f + sxp[t + DW_PAD][tid];
            float s = (v >= 1.0f) ? 1.0f : 0.0f;
            v = (s > 0.0f) ? 0.0f : v;
            sxp[t + DW_PAD][tid] = s;
        }
    }
    __syncthreads();

    {
        int ci = tid & 63;
        int tg = tid >> 6;
        int c  = c0 + ci;
        int t0 = tg * 32;

        float wr[K_DW];
        #pragma unroll
        for (int k = 0; k < K_DW; k++) wr[k] = w[c * K_DW + k];
        float bb = bvec[c];

        float acc[32];
        #pragma unroll
        for (int i = 0; i < 32; i++) acc[i] = bb;

        #pragma unroll
        for (int dt = -DW_PAD; dt <= 31 + DW_PAD; dt++) {
            float sv = sxp[t0 + dt + DW_PAD][ci];
            #pragma unroll
            for (int i = 0; i < 32; i++) {
                int k = dt - i + DW_PAD;
                if (k >= 0 && k < K_DW) acc[i] += sv * wr[k];
            }
        }
        __syncthreads();
        #pragma unroll
        for (int i = 0; i < 32; i++) sd[t0 + i][ci] = acc[i];
    }
    __syncthreads();

    char* sout = (char*)smraw;
    if (tid < 64) {
        int c = c0 + tid;
        float g = bn2p[c], be = bn2p[C_DIM + c], mm = bn2p[2 * C_DIM + c], vv = bn2p[3 * C_DIM + c];
        float sc = g / sqrtf(vv + EPSF);
        float sh = be - mm * sc;
        float v = 0.0f;
        #pragma unroll 4
        for (int t = 0; t < T_DIM; t++) {
            float xv = sd[t][tid] * sc + sh;
            v = v * 0.5f + xv;
            float s = (v >= 1.0f) ? 1.0f : 0.0f;
            v = (s > 0.0f) ? 0.0f : v;
            sout[t * 64 + tid] = (char)(s > 0.0f ? 1 : 0);
        }
    }
    __syncthreads();

    for (int i = tid; i < T_DIM * 64; i += 256) {
        int t = i >> 6, ci = i & 63;
        S2i[((size_t)t * B_DIM + b) * C_DIM + c0 + ci] = sout[t * 64 + ci];
    }
}

// ---------------- gate LIF -> s8 spikes ----------------
__global__ void __launch_bounds__(384) gate_kernel(
    const float* __restrict__ Y2, char* __restrict__ Sgi)
{
    int b = blockIdx.x;
    int c = blockIdx.y * 384 + threadIdx.x;
    const float* xp = Y2 + (size_t)b * 2 * C_DIM + C_DIM + c;
    size_t stx = (size_t)B_DIM * 2 * C_DIM;

    float v = 0.0f;
    #pragma unroll 4
    for (int t = 0; t < T_DIM; t++) {
        float xv = xp[(size_t)t * stx];
        v = v * 0.5f + xv;
        float s = (v >= 1.0f) ? 1.0f : 0.0f;
        v = (s > 0.0f) ? 0.0f : v;
        Sgi[((size_t)t * B_DIM + b) * C_DIM + c] = (char)(s > 0.0f ? 1 : 0);
    }
}

// ---------------- fused final double-LIF ----------------
__global__ void __launch_bounds__(256) lif_final_kernel(
    const float* __restrict__ Y3, const float* __restrict__ Y2out,
    float* __restrict__ Out)
{
    int j = blockIdx.x * blockDim.x + threadIdx.x;
    if (j >= B_DIM * C_DIM) return;
    int b = j / C_DIM, c = j % C_DIM;
    const float* yp = Y3 + (size_t)b * C_DIM + c;
    const float* op = Y2out + (size_t)b * 2 * C_DIM + c;
    float* sp = Out + (size_t)j;
    size_t st3 = (size_t)B_DIM * C_DIM;
    size_t st2 = (size_t)B_DIM * 2 * C_DIM;

    float v9 = 0.0f, v10 = 0.0f;
    #pragma unroll 4
    for (int t = 0; t < T_DIM; t++) {
        float g = yp[(size_t)t * st3];
        v9 = v9 * 0.5f + g;
        float s9 = (v9 >= 1.0f) ? 1.0f : 0.0f;
        v9 = (s9 > 0.0f) ? 0.0f : v9;
        float x = op[(size_t)t * st2] * s9;
        v10 = v10 * 0.5f + x;
        float s10 = (v10 >= 1.0f) ? 1.0f : 0.0f;
        v10 = (s10 > 0.0f) ? 0.0f : v10;
        sp[(size_t)t * st3] = s10;
    }
}

// ---------------- launch ----------------
extern "C" void kernel_launch(void* const* d_in, const int* in_sizes, int n_in,
                              void* d_out, int out_size)
{
    const float* x        = (const float*)d_in[0];
    const float* ln_g     = (const float*)d_in[1];
    const float* ln_b     = (const float*)d_in[2];
    const float* pw1_w    = (const float*)d_in[3];
    const float* pw1_b    = (const float*)d_in[4];
    const float* bn1_p    = (const float*)d_in[5];
    const float* dw_w     = (const float*)d_in[6];
    const float* dw_b     = (const float*)d_in[7];
    const float* bn2_p    = (const float*)d_in[8];
    const float* pw2_w    = (const float*)d_in[9];
    const float* pw2_b    = (const float*)d_in[10];
    const float* bn3_p    = (const float*)d_in[11];
    const float* gsu_w    = (const float*)d_in[12];
    const float* gsu_b    = (const float*)d_in[13];
    const float* gsu_bn_p = (const float*)d_in[14];

    float *Y1, *Y2, *Y3, *D2, *Dg;
    char *S2i, *Sgi, *W2d0, *W2d1, *W2d2, *W2d3, *Wgd0, *Wgd1, *Wgd2, *Wgd3;
    __nv_bfloat16 *Hh, *Hm, *Hl, *W1hi, *W1mi, *W1lo;
    cudaGetSymbolAddress((void**)&Y1,   g_Y1);
    cudaGetSymbolAddress((void**)&Y2,   g_Y2);
    cudaGetSymbolAddress((void**)&Y3,   g_Y3);
    cudaGetSymbolAddress((void**)&S2i,  g_S2i);
    cudaGetSymbolAddress((void**)&Sgi,  g_Sgi);
    cudaGetSymbolAddress((void**)&D2,   g_D2);
    cudaGetSymbolAddress((void**)&Dg,   g_Dg);
    cudaGetSymbolAddress((void**)&Hh,   g_Hh);
    cudaGetSymbolAddress((void**)&Hm,   g_Hm);
    cudaGetSymbolAddress((void**)&Hl,   g_Hl);
    cudaGetSymbolAddress((void**)&W1hi, g_W1hi);
    cudaGetSymbolAddress((void**)&W1mi, g_W1mi);
    cudaGetSymbolAddress((void**)&W1lo, g_W1lo);
    char* base2; cudaGetSymbolAddress((void**)&base2, g_W2d);
    W2d0 = base2; W2d1 = base2 + (size_t)2*C_DIM*C_DIM;
    W2d2 = base2 + (size_t)4*C_DIM*C_DIM; W2d3 = base2 + (size_t)6*C_DIM*C_DIM;
    char* baseg; cudaGetSymbolAddress((void**)&baseg, g_Wgd);
    Wgd0 = baseg; Wgd1 = baseg + (size_t)C_DIM*C_DIM;
    Wgd2 = baseg + (size_t)2*C_DIM*C_DIM; Wgd3 = baseg + (size_t)3*C_DIM*C_DIM;

    cudaFuncSetAttribute(gemm_split6_bf16,
        cudaFuncAttributeMaxDynamicSharedMemorySize, S6_SMEM);
    cudaFuncSetAttribute(gemm_spike_i8,
        cudaFuncAttributeMaxDynamicSharedMemorySize, I8_SMEM);
    cudaFuncSetAttribute(lifdw_kernel,
        cudaFuncAttributeMaxDynamicSharedMemorySize, LIFDW_SMEM);

    const int lif_blocks = (B_DIM * C_DIM + 255) / 256;   // 192

    // 0) W1 split + W2/Wg digit decompositions
    split_w_kernel<<<(C_DIM * C_DIM + 255) / 256, 256>>>(pw1_w, W1hi, W1mi, W1lo, C_DIM * C_DIM);
    digit_kernel<<<(2 * C_DIM + 7) / 8, 256>>>(pw2_w, W2d0, W2d1, W2d2, W2d3, D2, 2 * C_DIM, C_DIM);
    digit_kernel<<<(C_DIM + 7) / 8, 256>>>(gsu_w, Wgd0, Wgd1, Wgd2, Wgd3, Dg, C_DIM, C_DIM);

    // 1) LayerNorm -> H splits
    ln_kernel<<<M_DIM, 256>>>(x, ln_g, ln_b, Hh, Hm, Hl);

    // 2) pw1 + bias + bn1 (dense bf16 6-term mma)
    gemm_split6_bf16<<<dim3(C_DIM / GBN, M_DIM / GBM), 256, S6_SMEM>>>(
        Hh, Hm, Hl, W1hi, W1mi, W1lo, pw1_b, bn1_p, Y1, M_DIM, C_DIM, C_DIM);

    // 3-5) fused: lif1 -> depthwise -> bn2+lif2 -> s8 spikes
    lifdw_kernel<<<dim3(B_DIM, C_DIM / 64), 256, LIFDW_SMEM>>>(
        Y1, dw_w, dw_b, bn2_p, S2i);

    // 6) pw2 + bias + bn3 (int8 single-pass 4-digit mma)
    gemm_spike_i8<<<dim3(2 * C_DIM / GBN, M_DIM / GBM), 256, I8_SMEM>>>(
        S2i, W2d0, W2d1, W2d2, W2d3, D2, pw2_b, bn3_p, Y2, M_DIM, 2 * C_DIM, C_DIM);

    // 7) gate LIF -> s8 spikes
    gate_kernel<<<dim3(B_DIM, 2), 384>>>(Y2, Sgi);

    // 8) gsu GEMM (int8 single-pass 4-digit mma)
    gemm_spike_i8<<<dim3(C_DIM / GBN, M_DIM / GBM), 256, I8_SMEM>>>(
        Sgi, Wgd0, Wgd1, Wgd2, Wgd3, Dg, gsu_b, gsu_bn_p, Y3, M_DIM, C_DIM, C_DIM);

    // 9+10) fused final double-LIF
    lif_final_kernel<<<lif_blocks, 256>>>(Y3, Y2, (float*)d_out);
}

// round 17
// speedup vs baseline: 1.7603x; 1.0213x over previous
#include <cuda_runtime.h>
#include <cuda_bf16.h>
#include <math.h>

#define T_DIM 128
#define B_DIM 64
#define C_DIM 768
#define M_DIM (T_DIM * B_DIM)   // 8192
#define K_DW  31
#define EPSF  1e-5f

typedef unsigned long long ull;
typedef unsigned int uint32;
typedef unsigned short ushort;

// ---------------- scratch ----------------
__device__ float g_Y1 [M_DIM * C_DIM];
__device__ float g_Y2 [M_DIM * 2 * C_DIM];
__device__ float g_Y3 [M_DIM * C_DIM];
__device__ char  g_S2i[M_DIM * C_DIM];
__device__ char  g_Sgi[M_DIM * C_DIM];
__device__ char  g_W2d[4][2 * C_DIM * C_DIM];
__device__ char  g_Wgd[4][C_DIM * C_DIM];
__device__ float g_D2 [2 * C_DIM];
__device__ float g_Dg [C_DIM];
__device__ __nv_bfloat16 g_Hh[M_DIM * C_DIM];
__device__ __nv_bfloat16 g_Hm[M_DIM * C_DIM];
__device__ __nv_bfloat16 g_Hl[M_DIM * C_DIM];
__device__ __nv_bfloat16 g_W1hi[C_DIM * C_DIM];
__device__ __nv_bfloat16 g_W1mi[C_DIM * C_DIM];
__device__ __nv_bfloat16 g_W1lo[C_DIM * C_DIM];

// ---------------- helpers ----------------
__device__ __forceinline__ void mma_bf16(float* c, const uint32* a, uint32 b0, uint32 b1) {
    asm volatile(
        "mma.sync.aligned.m16n8k16.row.col.f32.bf16.bf16.f32 "
        "{%0,%1,%2,%3}, {%4,%5,%6,%7}, {%8,%9}, {%0,%1,%2,%3};"
        : "+f"(c[0]), "+f"(c[1]), "+f"(c[2]), "+f"(c[3])
        : "r"(a[0]), "r"(a[1]), "r"(a[2]), "r"(a[3]), "r"(b0), "r"(b1));
}
__device__ __forceinline__ void mma_s8(int* c, const uint32* a, uint32 b0, uint32 b1) {
    asm volatile(
        "mma.sync.aligned.m16n8k32.row.col.s32.s8.s8.s32 "
        "{%0,%1,%2,%3}, {%4,%5,%6,%7}, {%8,%9}, {%0,%1,%2,%3};"
        : "+r"(c[0]), "+r"(c[1]), "+r"(c[2]), "+r"(c[3])
        : "r"(a[0]), "r"(a[1]), "r"(a[2]), "r"(a[3]), "r"(b0), "r"(b1));
}
__device__ __forceinline__ void ldsm4(uint32* r, uint32 saddr) {
    asm volatile("ldmatrix.sync.aligned.m8n8.x4.shared.b16 {%0,%1,%2,%3}, [%4];"
        : "=r"(r[0]), "=r"(r[1]), "=r"(r[2]), "=r"(r[3]) : "r"(saddr));
}
#define CP16(dst, src) \
    asm volatile("cp.async.cg.shared.global [%0], [%1], 16;" :: "r"(dst), "l"(src))
#define CP_COMMIT() asm volatile("cp.async.commit_group;" ::: "memory")
#define CP_WAIT1()  asm volatile("cp.async.wait_group 1;" ::: "memory")

// ---------------- weight split (W1) ----------------
__global__ void __launch_bounds__(256) split_w_kernel(
    const float* __restrict__ W,
    __nv_bfloat16* __restrict__ hi, __nv_bfloat16* __restrict__ mi,
    __nv_bfloat16* __restrict__ lo, int n)
{
    int i = blockIdx.x * blockDim.x + threadIdx.x;
    if (i >= n) return;
    float w = W[i];
    __nv_bfloat16 h = __float2bfloat16(w);
    float r1 = w - __bfloat162float(h);
    __nv_bfloat16 m = __float2bfloat16(r1);
    float r2 = r1 - __bfloat162float(m);
    hi[i] = h; mi[i] = m; lo[i] = __float2bfloat16(r2);
}

// ---------------- 4-digit base-128 decomposition, per output row -------------
__global__ void __launch_bounds__(256) digit_kernel(
    const float* __restrict__ W,
    char* __restrict__ d0, char* __restrict__ d1,
    char* __restrict__ d2, char* __restrict__ d3,
    float* __restrict__ Dsc, int N, int K)
{
    int row = blockIdx.x * 8 + (threadIdx.x >> 5);
    int lane = threadIdx.x & 31;
    if (row >= N) return;
    const float* wr = W + (size_t)row * K;

    float mx = 0.0f;
    for (int k = lane; k < K; k += 32) mx = fmaxf(mx, fabsf(wr[k]));
    #pragma unroll
    for (int o = 16; o > 0; o >>= 1) mx = fmaxf(mx, __shfl_xor_sync(0xffffffffu, mx, o));

    int e; frexpf(mx, &e);
    float D = exp2f((float)(e + 1));
    float inv = 1.0f / D;
    if (lane == 0) Dsc[row] = D;

    for (int k = lane; k < K; k += 32) {
        float f = wr[k] * inv;
        f *= 128.0f; float q1 = rintf(f); f -= q1;
        f *= 128.0f; float q2 = rintf(f); f -= q2;
        f *= 128.0f; float q3 = rintf(f); f -= q3;
        f *= 128.0f; float q4 = rintf(f);
        size_t idx = (size_t)row * K + k;
        d0[idx] = (char)(int)q1; d1[idx] = (char)(int)q2;
        d2[idx] = (char)(int)q3; d3[idx] = (char)(int)q4;
    }
}

// ---------------- block reduction helper ----------------
__inline__ __device__ float block_reduce_sum(float val, float* shmem) {
    int tid = threadIdx.x;
    #pragma unroll
    for (int o = 16; o > 0; o >>= 1) val += __shfl_xor_sync(0xffffffffu, val, o);
    if ((tid & 31) == 0) shmem[tid >> 5] = val;
    __syncthreads();
    float r = 0.0f;
    if (tid < 8) r = shmem[tid];
    if (tid < 32) {
        #pragma unroll
        for (int o = 4; o > 0; o >>= 1) r += __shfl_xor_sync(0xffffffffu, r, o);
    }
    if (tid == 0) shmem[0] = r;
    __syncthreads();
    r = shmem[0];
    __syncthreads();
    return r;
}

// ---------------- layernorm -> 3-way bf16 split output ----------------
__global__ void __launch_bounds__(256) ln_kernel(
    const float* __restrict__ x, const float* __restrict__ gam,
    const float* __restrict__ bet,
    __nv_bfloat16* __restrict__ Hh, __nv_bfloat16* __restrict__ Hm,
    __nv_bfloat16* __restrict__ Hl)
{
    __shared__ float red[32];
    int row = blockIdx.x;
    const float* xr = x + (size_t)row * C_DIM;
    int tid = threadIdx.x;

    float lx[3];
    float s = 0.0f;
    #pragma unroll
    for (int i = 0; i < 3; i++) { lx[i] = xr[tid + i * 256]; s += lx[i]; }
    float mean = block_reduce_sum(s, red) * (1.0f / C_DIM);

    float s2 = 0.0f;
    #pragma unroll
    for (int i = 0; i < 3; i++) { float d = lx[i] - mean; s2 += d * d; }
    float var = block_reduce_sum(s2, red) * (1.0f / C_DIM);
    float rstd = 1.0f / sqrtf(var + EPSF);

    #pragma unroll
    for (int i = 0; i < 3; i++) {
        int c = tid + i * 256;
        float y = (lx[i] - mean) * rstd * gam[c] + bet[c];
        __nv_bfloat16 h = __float2bfloat16(y);
        float r1 = y - __bfloat162float(h);
        __nv_bfloat16 m = __float2bfloat16(r1);
        float r2 = r1 - __bfloat162float(m);
        size_t idx = (size_t)row * C_DIM + c;
        Hh[idx] = h; Hm[idx] = m; Hl[idx] = __float2bfloat16(r2);
    }
}

// ================= dense GEMM1 (6-term bf16 split, mma) =================
#define GBM 128
#define GBN 64
#define GBK 32
#define ASTR 40

#define S6_AH (GBM * ASTR)
#define S6_BH (GBN * ASTR)
#define S6_STG (3 * S6_AH + 3 * S6_BH)
#define S6_SMEM (2 * S6_STG * 2)

__global__ void __launch_bounds__(256) gemm_split6_bf16(
    const __nv_bfloat16* __restrict__ Ah, const __nv_bfloat16* __restrict__ Am,
    const __nv_bfloat16* __restrict__ Al,
    const __nv_bfloat16* __restrict__ Wh, const __nv_bfloat16* __restrict__ Wm,
    const __nv_bfloat16* __restrict__ Wl,
    const float* __restrict__ bias, const float* __restrict__ bnp,
    float* __restrict__ Out, int M, int N, int K)
{
    extern __shared__ __align__(16) unsigned short sm[];
    uint32 smb = (uint32)__cvta_generic_to_shared(sm);

    int tid = threadIdx.x;
    int wid = tid >> 5, lane = tid & 31;
    int wm = wid & 3, wn = wid >> 2;
    int bn0 = blockIdx.x * GBN, bm0 = blockIdx.y * GBM;

    int ldrow = tid >> 2;
    int ldcol = (tid & 3) * 8;

    const __nv_bfloat16* Asel[3] = {Ah, Am, Al};
    const __nv_bfloat16* Wsel[3] = {Wh, Wm, Wl};

    float acc[2][4][4];
    #pragma unroll
    for (int mt = 0; mt < 2; mt++)
        #pragma unroll
        for (int nt = 0; nt < 4; nt++)
            #pragma unroll
            for (int q = 0; q < 4; q++) acc[mt][nt][q] = 0.0f;

    int a_row = (lane & 7) + ((lane >> 3) & 1) * 8;
    int a_ko  = ((lane >> 4) & 1) * 8;
    int b_row = (lane & 7) + ((lane >> 4) & 1) * 8;
    int b_ko  = ((lane >> 3) & 1) * 8;

    auto issue = [&](int st, int k0) {
        #pragma unroll
        for (int s = 0; s < 3; s++) {
            #pragma unroll
            for (int j = 0; j < 2; j++) {
                int row = ldrow + j * 64;
                uint32 dst = smb + (uint32)(st * S6_STG + s * S6_AH + row * ASTR + ldcol) * 2;
                CP16(dst, Asel[s] + (size_t)(bm0 + row) * K + k0 + ldcol);
            }
            uint32 dst = smb + (uint32)(st * S6_STG + 3 * S6_AH + s * S6_BH + ldrow * ASTR + ldcol) * 2;
            CP16(dst, Wsel[s] + (size_t)(bn0 + ldrow) * K + k0 + ldcol);
        }
    };

    int NCH = K / GBK;
    issue(0, 0);
    CP_COMMIT();

    for (int ch = 0; ch < NCH; ch++) {
        if (ch + 1 < NCH) issue((ch + 1) & 1, (ch + 1) * GBK);
        CP_COMMIT();
        CP_WAIT1();
        __syncthreads();

        int st = ch & 1;
        uint32 abase = smb + (uint32)(st * S6_STG) * 2;
        uint32 bbase = smb + (uint32)(st * S6_STG + 3 * S6_AH) * 2;

        #pragma unroll
        for (int ks = 0; ks < 2; ks++) {
            int kc = ks * 16;
            uint32 af[3][2][4];
            #pragma unroll
            for (int s = 0; s < 3; s++)
                #pragma unroll
                for (int mt = 0; mt < 2; mt++)
                    ldsm4(af[s][mt], abase + (uint32)(s * S6_AH + (wm * 32 + mt * 16 + a_row) * ASTR + kc + a_ko) * 2);
            #pragma unroll
            for (int t = 0; t < 3; t++) {
                #pragma unroll
                for (int g = 0; g < 2; g++) {
                    uint32 bf[4];
                    ldsm4(bf, bbase + (uint32)(t * S6_BH + (wn * 32 + g * 16 + b_row) * ASTR + kc + b_ko) * 2);
                    #pragma unroll
                    for (int s = 0; s < 3; s++) {
                        if (s + t <= 2) {
                            mma_bf16(acc[0][2 * g],     af[s][0], bf[0], bf[1]);
                            mma_bf16(acc[1][2 * g],     af[s][1], bf[0], bf[1]);
                            mma_bf16(acc[0][2 * g + 1], af[s][0], bf[2], bf[3]);
                            mma_bf16(acc[1][2 * g + 1], af[s][1], bf[2], bf[3]);
                        }
                    }
                }
            }
        }
        __syncthreads();
    }

    int r4 = lane >> 2, c2 = (lane & 3) * 2;
    #pragma unroll
    for (int nt = 0; nt < 4; nt++) {
        int n0 = bn0 + wn * 32 + nt * 8 + c2;
        float g0 = bnp[n0],     be0 = bnp[N + n0],     mm0 = bnp[2*N + n0],     vv0 = bnp[3*N + n0];
        float g1 = bnp[n0 + 1], be1 = bnp[N + n0 + 1], mm1 = bnp[2*N + n0 + 1], vv1 = bnp[3*N + n0 + 1];
        float sc0 = g0 / sqrtf(vv0 + EPSF), sh0 = be0 - mm0 * sc0;
        float sc1 = g1 / sqrtf(vv1 + EPSF), sh1 = be1 - mm1 * sc1;
        float bs0 = bias[n0], bs1 = bias[n0 + 1];
        #pragma unroll
        for (int mt = 0; mt < 2; mt++) {
            int m0 = bm0 + wm * 32 + mt * 16 + r4;
            float2 o0, o1;
            o0.x = (acc[mt][nt][0] + bs0) * sc0 + sh0;
            o0.y = (acc[mt][nt][1] + bs1) * sc1 + sh1;
            o1.x = (acc[mt][nt][2] + bs0) * sc0 + sh0;
            o1.y = (acc[mt][nt][3] + bs1) * sc1 + sh1;
            *(float2*)&Out[(size_t)m0 * N + n0] = o0;
            *(float2*)&Out[(size_t)(m0 + 8) * N + n0] = o1;
        }
    }
}

// ================= int8 spike GEMM: single pass, 3-stage pipeline ===========
// Out[m,n] = bn( D_n * sum_d 128^-(d+1) * (Σ_k spike*q_d) + bias )
// 3 smem stages, ONE __syncthreads per chunk (stage written at iter ch is the
// stage read at iter ch-1; the top barrier orders it). Unconditional commits
// keep wait_group 1 exact through the tail.
#define I8_ASTR 80                       // bytes per smem row
#define I8_AH  (GBM * I8_ASTR)           // 10240
#define I8_BH  (GBN * I8_ASTR)           // 5120
#define I8_STG (I8_AH + 4 * I8_BH)       // 30720
#define I8_SMEM (3 * I8_STG)             // 92160

__global__ void __launch_bounds__(256) gemm_spike_i8(
    const char* __restrict__ A,
    const char* __restrict__ d0, const char* __restrict__ d1,
    const char* __restrict__ d2, const char* __restrict__ d3,
    const float* __restrict__ Dsc,
    const float* __restrict__ bias, const float* __restrict__ bnp,
    float* __restrict__ Out, int M, int N, int K)
{
    extern __shared__ __align__(16) char smi[];
    uint32 smb = (uint32)__cvta_generic_to_shared(smi);

    int tid = threadIdx.x;
    int wid = tid >> 5, lane = tid & 31;
    int wm = wid & 3, wn = wid >> 2;
    int bn0 = blockIdx.x * GBN, bm0 = blockIdx.y * GBM;

    const char* digs[4] = {d0, d1, d2, d3};

    int acc[4][2][4][4];
    #pragma unroll
    for (int d = 0; d < 4; d++)
        #pragma unroll
        for (int mt = 0; mt < 2; mt++)
            #pragma unroll
            for (int nt = 0; nt < 4; nt++)
                #pragma unroll
                for (int q = 0; q < 4; q++) acc[d][mt][nt][q] = 0;

    int a_row = (lane & 7) + ((lane >> 3) & 1) * 8;
    int a_kb  = ((lane >> 4) & 1) * 16;
    int b_row = (lane & 7) + ((lane >> 4) & 1) * 8;
    int b_kb  = ((lane >> 3) & 1) * 16;

    int arow = tid >> 2, acg = (tid & 3) * 16;

    auto issue = [&](int st, int k0) {
        #pragma unroll
        for (int j = 0; j < 2; j++) {
            int row = arow + j * 64;
            uint32 dst = smb + (uint32)(st * I8_STG + row * I8_ASTR + acg);
            CP16(dst, A + (size_t)(bm0 + row) * K + k0 + acg);
        }
        #pragma unroll
        for (int d = 0; d < 4; d++) {
            uint32 dst = smb + (uint32)(st * I8_STG + I8_AH + d * I8_BH + arow * I8_ASTR + acg);
            CP16(dst, digs[d] + (size_t)(bn0 + arow) * K + k0 + acg);
        }
    };

    int NCH = K / 64;                 // 12 chunks of 64 s8
    issue(0, 0);   CP_COMMIT();
    issue(1, 64);  CP_COMMIT();

    for (int ch = 0; ch < NCH; ch++) {
        CP_WAIT1();
        __syncthreads();

        if (ch + 2 < NCH) issue((ch + 2) % 3, (ch + 2) * 64);
        CP_COMMIT();      // unconditional: keeps group count aligned at tail

        int st = ch % 3;
        uint32 abase = smb + (uint32)(st * I8_STG);
        uint32 bbase = smb + (uint32)(st * I8_STG + I8_AH);

        #pragma unroll
        for (int ks = 0; ks < 2; ks++) {
            int kc = ks * 32;
            uint32 af[2][4];
            #pragma unroll
            for (int mt = 0; mt < 2; mt++)
                ldsm4(af[mt], abase + (uint32)((wm * 32 + mt * 16 + a_row) * I8_ASTR + kc + a_kb));
            #pragma unroll
            for (int d = 0; d < 4; d++) {
                #pragma unroll
                for (int g = 0; g < 2; g++) {
                    uint32 bf[4];
                    ldsm4(bf, bbase + (uint32)(d * I8_BH + (wn * 32 + g * 16 + b_row) * I8_ASTR + kc + b_kb));
                    mma_s8(acc[d][0][2 * g],     af[0], bf[0], bf[1]);
                    mma_s8(acc[d][1][2 * g],     af[1], bf[0], bf[1]);
                    mma_s8(acc[d][0][2 * g + 1], af[0], bf[2], bf[3]);
                    mma_s8(acc[d][1][2 * g + 1], af[1], bf[2], bf[3]);
                }
            }
        }
    }

    // epilogue: combine digits (order d0..d3, unchanged)
    int r4 = lane >> 2, c2 = (lane & 3) * 2;
    #pragma unroll
    for (int nt = 0; nt < 4; nt++) {
        int n0 = bn0 + wn * 32 + nt * 8 + c2;
        float facc[2][4];
        #pragma unroll
        for (int mt = 0; mt < 2; mt++)
            #pragma unroll
            for (int q = 0; q < 4; q++) facc[mt][q] = 0.0f;
        #pragma unroll
        for (int d = 0; d < 4; d++) {
            float psc = exp2f(-7.0f * (float)(d + 1));
            float c0 = Dsc[n0] * psc;
            float c1 = Dsc[n0 + 1] * psc;
            #pragma unroll
            for (int mt = 0; mt < 2; mt++) {
                facc[mt][0] += c0 * (float)acc[d][mt][nt][0];
                facc[mt][1] += c1 * (float)acc[d][mt][nt][1];
                facc[mt][2] += c0 * (float)acc[d][mt][nt][2];
                facc[mt][3] += c1 * (float)acc[d][mt][nt][3];
            }
        }
        float g0 = bnp[n0],     be0 = bnp[N + n0],     mm0 = bnp[2*N + n0],     vv0 = bnp[3*N + n0];
        float g1 = bnp[n0 + 1], be1 = bnp[N + n0 + 1], mm1 = bnp[2*N + n0 + 1], vv1 = bnp[3*N + n0 + 1];
        float sc0 = g0 / sqrtf(vv0 + EPSF), sh0 = be0 - mm0 * sc0;
        float sc1 = g1 / sqrtf(vv1 + EPSF), sh1 = be1 - mm1 * sc1;
        float bs0 = bias[n0], bs1 = bias[n0 + 1];
        #pragma unroll
        for (int mt = 0; mt < 2; mt++) {
            int m0 = bm0 + wm * 32 + mt * 16 + r4;
            float2 o0, o1;
            o0.x = (facc[mt][0] + bs0) * sc0 + sh0;
            o0.y = (facc[mt][1] + bs1) * sc1 + sh1;
            o1.x = (facc[mt][2] + bs0) * sc0 + sh0;
            o1.y = (facc[mt][3] + bs1) * sc1 + sh1;
            *(float2*)&Out[(size_t)m0 * N + n0] = o0;
            *(float2*)&Out[(size_t)(m0 + 8) * N + n0] = o1;
        }
    }
}

// ---------------- fused lif1 -> depthwise -> bn2+lif2 -> s8 spikes -----------
#define DW_PAD 15
#define LD_SXP_ROWS (T_DIM + 2 * DW_PAD)
#define LIFDW_SMEM (LD_SXP_ROWS * 64 * 4 + T_DIM * 64 * 4)

__global__ void __launch_bounds__(256) lifdw_kernel(
    const float* __restrict__ Y1, const float* __restrict__ w,
    const float* __restrict__ bvec, const float* __restrict__ bn2p,
    char* __restrict__ S2i)
{
    extern __shared__ __align__(16) char smraw[];
    float (*sxp)[64] = (float(*)[64])smraw;
    float (*sd)[64]  = (float(*)[64])(smraw + LD_SXP_ROWS * 64 * 4);

    int b  = blockIdx.x;
    int c0 = blockIdx.y * 64;
    int tid = threadIdx.x;

    for (int i = tid; i < 2 * DW_PAD * 64; i += 256) {
        int r = i >> 6, ci = i & 63;
        if (r < DW_PAD) sxp[r][ci] = 0.0f;
        else            sxp[T_DIM + DW_PAD + (r - DW_PAD)][ci] = 0.0f;
    }
    for (int i = tid; i < T_DIM * 64; i += 256) {
        int t = i >> 6, ci = i & 63;
        sxp[t + DW_PAD][ci] = Y1[((size_t)t * B_DIM + b) * C_DIM + c0 + ci];
    }
    __syncthreads();

    if (tid < 64) {
        float v = 0.0f;
        #pragma unroll 4
        for (int t = 0; t < T_DIM; t++) {
            v = v * 0.5f + sxp[t + DW_PAD][tid];
            float s = (v >= 1.0f) ? 1.0f : 0.0f;
            v = (s > 0.0f) ? 0.0f : v;
            sxp[t + DW_PAD][tid] = s;
        }
    }
    __syncthreads();

    {
        int ci = tid & 63;
        int tg = tid >> 6;
        int c  = c0 + ci;
        int t0 = tg * 32;

        float wr[K_DW];
        #pragma unroll
        for (int k = 0; k < K_DW; k++) wr[k] = w[c * K_DW + k];
        float bb = bvec[c];

        float acc[32];
        #pragma unroll
        for (int i = 0; i < 32; i++) acc[i] = bb;

        #pragma unroll
        for (int dt = -DW_PAD; dt <= 31 + DW_PAD; dt++) {
            float sv = sxp[t0 + dt + DW_PAD][ci];
            #pragma unroll
            for (int i = 0; i < 32; i++) {
                int k = dt - i + DW_PAD;
                if (k >= 0 && k < K_DW) acc[i] += sv * wr[k];
            }
        }
        __syncthreads();
        #pragma unroll
        for (int i = 0; i < 32; i++) sd[t0 + i][ci] = acc[i];
    }
    __syncthreads();

    char* sout = (char*)smraw;
    if (tid < 64) {
        int c = c0 + tid;
        float g = bn2p[c], be = bn2p[C_DIM + c], mm = bn2p[2 * C_DIM + c], vv = bn2p[3 * C_DIM + c];
        float sc = g / sqrtf(vv + EPSF);
        float sh = be - mm * sc;
        float v = 0.0f;
        #pragma unroll 4
        for (int t = 0; t < T_DIM; t++) {
            float xv = sd[t][tid] * sc + sh;
            v = v * 0.5f + xv;
            float s = (v >= 1.0f) ? 1.0f : 0.0f;
            v = (s > 0.0f) ? 0.0f : v;
            sout[t * 64 + tid] = (char)(s > 0.0f ? 1 : 0);
        }
    }
    __syncthreads();

    for (int i = tid; i < T_DIM * 64; i += 256) {
        int t = i >> 6, ci = i & 63;
        S2i[((size_t)t * B_DIM + b) * C_DIM + c0 + ci] = sout[t * 64 + ci];
    }
}

// ---------------- gate LIF -> s8 spikes ----------------
__global__ void __launch_bounds__(384) gate_kernel(
    const float* __restrict__ Y2, char* __restrict__ Sgi)
{
    int b = blockIdx.x;
    int c = blockIdx.y * 384 + threadIdx.x;
    const float* xp = Y2 + (size_t)b * 2 * C_DIM + C_DIM + c;
    size_t stx = (size_t)B_DIM * 2 * C_DIM;

    float v = 0.0f;
    #pragma unroll 4
    for (int t = 0; t < T_DIM; t++) {
        float xv = xp[(size_t)t * stx];
        v = v * 0.5f + xv;
        float s = (v >= 1.0f) ? 1.0f : 0.0f;
        v = (s > 0.0f) ? 0.0f : v;
        Sgi[((size_t)t * B_DIM + b) * C_DIM + c] = (char)(s > 0.0f ? 1 : 0);
    }
}

// ---------------- fused final double-LIF ----------------
__global__ void __launch_bounds__(256) lif_final_kernel(
    const float* __restrict__ Y3, const float* __restrict__ Y2out,
    float* __restrict__ Out)
{
    int j = blockIdx.x * blockDim.x + threadIdx.x;
    if (j >= B_DIM * C_DIM) return;
    int b = j / C_DIM, c = j % C_DIM;
    const float* yp = Y3 + (size_t)b * C_DIM + c;
    const float* op = Y2out + (size_t)b * 2 * C_DIM + c;
    float* sp = Out + (size_t)j;
    size_t st3 = (size_t)B_DIM * C_DIM;
    size_t st2 = (size_t)B_DIM * 2 * C_DIM;

    float v9 = 0.0f, v10 = 0.0f;
    #pragma unroll 4
    for (int t = 0; t < T_DIM; t++) {
        float g = yp[(size_t)t * st3];
        v9 = v9 * 0.5f + g;
        float s9 = (v9 >= 1.0f) ? 1.0f : 0.0f;
        v9 = (s9 > 0.0f) ? 0.0f : v9;
        float x = op[(size_t)t * st2] * s9;
        v10 = v10 * 0.5f + x;
        float s10 = (v10 >= 1.0f) ? 1.0f : 0.0f;
        v10 = (s10 > 0.0f) ? 0.0f : v10;
        sp[(size_t)t * st3] = s10;
    }
}

// ---------------- launch ----------------
extern "C" void kernel_launch(void* const* d_in, const int* in_sizes, int n_in,
                              void* d_out, int out_size)
{
    const float* x        = (const float*)d_in[0];
    const float* ln_g     = (const float*)d_in[1];
    const float* ln_b     = (const float*)d_in[2];
    const float* pw1_w    = (const float*)d_in[3];
    const float* pw1_b    = (const float*)d_in[4];
    const float* bn1_p    = (const float*)d_in[5];
    const float* dw_w     = (const float*)d_in[6];
    const float* dw_b     = (const float*)d_in[7];
    const float* bn2_p    = (const float*)d_in[8];
    const float* pw2_w    = (const float*)d_in[9];
    const float* pw2_b    = (const float*)d_in[10];
    const float* bn3_p    = (const float*)d_in[11];
    const float* gsu_w    = (const float*)d_in[12];
    const float* gsu_b    = (const float*)d_in[13];
    const float* gsu_bn_p = (const float*)d_in[14];

    float *Y1, *Y2, *Y3, *D2, *Dg;
    char *S2i, *Sgi, *W2d0, *W2d1, *W2d2, *W2d3, *Wgd0, *Wgd1, *Wgd2, *Wgd3;
    __nv_bfloat16 *Hh, *Hm, *Hl, *W1hi, *W1mi, *W1lo;
    cudaGetSymbolAddress((void**)&Y1,   g_Y1);
    cudaGetSymbolAddress((void**)&Y2,   g_Y2);
    cudaGetSymbolAddress((void**)&Y3,   g_Y3);
    cudaGetSymbolAddress((void**)&S2i,  g_S2i);
    cudaGetSymbolAddress((void**)&Sgi,  g_Sgi);
    cudaGetSymbolAddress((void**)&D2,   g_D2);
    cudaGetSymbolAddress((void**)&Dg,   g_Dg);
    cudaGetSymbolAddress((void**)&Hh,   g_Hh);
    cudaGetSymbolAddress((void**)&Hm,   g_Hm);
    cudaGetSymbolAddress((void**)&Hl,   g_Hl);
    cudaGetSymbolAddress((void**)&W1hi, g_W1hi);
    cudaGetSymbolAddress((void**)&W1mi, g_W1mi);
    cudaGetSymbolAddress((void**)&W1lo, g_W1lo);
    char* base2; cudaGetSymbolAddress((void**)&base2, g_W2d);
    W2d0 = base2; W2d1 = base2 + (size_t)2*C_DIM*C_DIM;
    W2d2 = base2 + (size_t)4*C_DIM*C_DIM; W2d3 = base2 + (size_t)6*C_DIM*C_DIM;
    char* baseg; cudaGetSymbolAddress((void**)&baseg, g_Wgd);
    Wgd0 = baseg; Wgd1 = baseg + (size_t)C_DIM*C_DIM;
    Wgd2 = baseg + (size_t)2*C_DIM*C_DIM; Wgd3 = baseg + (size_t)3*C_DIM*C_DIM;

    cudaFuncSetAttribute(gemm_split6_bf16,
        cudaFuncAttributeMaxDynamicSharedMemorySize, S6_SMEM);
    cudaFuncSetAttribute(gemm_spike_i8,
        cudaFuncAttributeMaxDynamicSharedMemorySize, I8_SMEM);
    cudaFuncSetAttribute(lifdw_kernel,
        cudaFuncAttributeMaxDynamicSharedMemorySize, LIFDW_SMEM);

    const int lif_blocks = (B_DIM * C_DIM + 255) / 256;   // 192

    // 0) W1 split + W2/Wg digit decompositions
    split_w_kernel<<<(C_DIM * C_DIM + 255) / 256, 256>>>(pw1_w, W1hi, W1mi, W1lo, C_DIM * C_DIM);
    digit_kernel<<<(2 * C_DIM + 7) / 8, 256>>>(pw2_w, W2d0, W2d1, W2d2, W2d3, D2, 2 * C_DIM, C_DIM);
    digit_kernel<<<(C_DIM + 7) / 8, 256>>>(gsu_w, Wgd0, Wgd1, Wgd2, Wgd3, Dg, C_DIM, C_DIM);

    // 1) LayerNorm -> H splits
    ln_kernel<<<M_DIM, 256>>>(x, ln_g, ln_b, Hh, Hm, Hl);

    // 2) pw1 + bias + bn1 (dense bf16 6-term mma)
    gemm_split6_bf16<<<dim3(C_DIM / GBN, M_DIM / GBM), 256, S6_SMEM>>>(
        Hh, Hm, Hl, W1hi, W1mi, W1lo, pw1_b, bn1_p, Y1, M_DIM, C_DIM, C_DIM);

    // 3-5) fused: lif1 -> depthwise -> bn2+lif2 -> s8 spikes
    lifdw_kernel<<<dim3(B_DIM, C_DIM / 64), 256, LIFDW_SMEM>>>(
        Y1, dw_w, dw_b, bn2_p, S2i);

    // 6) pw2 + bias + bn3 (int8 single-pass, 3-stage)
    gemm_spike_i8<<<dim3(2 * C_DIM / GBN, M_DIM / GBM), 256, I8_SMEM>>>(
        S2i, W2d0, W2d1, W2d2, W2d3, D2, pw2_b, bn3_p, Y2, M_DIM, 2 * C_DIM, C_DIM);

    // 7) gate LIF -> s8 spikes
    gate_kernel<<<dim3(B_DIM, 2), 384>>>(Y2, Sgi);

    // 8) gsu GEMM (int8 single-pass, 3-stage)
    gemm_spike_i8<<<dim3(C_DIM / GBN, M_DIM / GBM), 256, I8_SMEM>>>(
        Sgi, Wgd0, Wgd1, Wgd2, Wgd3, Dg, gsu_b, gsu_bn_p, Y3, M_DIM, C_DIM, C_DIM);

    // 9+10) fused final double-LIF
    lif_final_kernel<<<lif_blocks, 256>>>(Y3, Y2, (float*)d_out);
}